// round 1
// baseline (speedup 1.0000x reference)
#include <cuda_runtime.h>

// Problem constants
#define BATCH   16
#define C_IN    256
#define HID     256
#define HEADS   8
#define DH      32
#define NPIX    4096
#define QKV_ROWS 768

// Scratch (device globals; no allocation allowed)
__device__ float g_qkv[BATCH * QKV_ROWS * NPIX];   // 192 MB
__device__ float g_ctx[BATCH * HEADS * DH * DH];   // 512 KB
__device__ float g_M  [BATCH * HID * HID];         // 4 MB
__device__ float g_y  [BATCH * HID * NPIX];        // 64 MB

// ---------------------------------------------------------------------------
// Classic 128x128x8 SGEMM, 256 threads, 8x8 per thread. K fixed = 256.
// A: [M,256] row-major (per-batch stride aStride; 0 => shared weights)
// B: [256,4096] row-major (per-batch stride bStride)
// C: [M,4096] row-major (per-batch stride cStride)
// ---------------------------------------------------------------------------
__global__ __launch_bounds__(256) void sgemm128(
    const float* __restrict__ A, const float* __restrict__ B, float* __restrict__ C,
    long aStride, long bStride, long cStride)
{
    __shared__ float As[8][128];
    __shared__ float Bs[8][128];

    const int tid = threadIdx.x;
    const int bx = blockIdx.x;   // n tile
    const int by = blockIdx.y;   // m tile
    const int bz = blockIdx.z;   // batch

    A += bz * aStride + (long)by * 128 * 256;
    B += bz * bStride + (long)bx * 128;
    C += bz * cStride + (long)by * 128 * 4096 + (long)bx * 128;

    const int arow = tid >> 1;          // 0..127
    const int acol = (tid & 1) * 4;     // 0 or 4
    const int brow = tid >> 5;          // 0..7
    const int bcol = (tid & 31) * 4;    // 0..124

    const int tx = tid & 15;
    const int ty = tid >> 4;

    float acc[8][8] = {};

    for (int kk = 0; kk < 256; kk += 8) {
        float4 av = *reinterpret_cast<const float4*>(A + (long)arow * 256 + kk + acol);
        float4 bv = *reinterpret_cast<const float4*>(B + (long)(kk + brow) * 4096 + bcol);
        __syncthreads();
        As[acol + 0][arow] = av.x;
        As[acol + 1][arow] = av.y;
        As[acol + 2][arow] = av.z;
        As[acol + 3][arow] = av.w;
        *reinterpret_cast<float4*>(&Bs[brow][bcol]) = bv;
        __syncthreads();

        #pragma unroll
        for (int k = 0; k < 8; ++k) {
            float4 a0 = *reinterpret_cast<const float4*>(&As[k][ty * 8]);
            float4 a1 = *reinterpret_cast<const float4*>(&As[k][ty * 8 + 4]);
            float4 b0 = *reinterpret_cast<const float4*>(&Bs[k][tx * 8]);
            float4 b1 = *reinterpret_cast<const float4*>(&Bs[k][tx * 8 + 4]);
            float am[8] = {a0.x, a0.y, a0.z, a0.w, a1.x, a1.y, a1.z, a1.w};
            float bn[8] = {b0.x, b0.y, b0.z, b0.w, b1.x, b1.y, b1.z, b1.w};
            #pragma unroll
            for (int i = 0; i < 8; ++i)
                #pragma unroll
                for (int j = 0; j < 8; ++j)
                    acc[i][j] += am[i] * bn[j];
        }
    }

    #pragma unroll
    for (int i = 0; i < 8; ++i) {
        float4 c0 = make_float4(acc[i][0], acc[i][1], acc[i][2], acc[i][3]);
        float4 c1 = make_float4(acc[i][4], acc[i][5], acc[i][6], acc[i][7]);
        float* crow = C + (long)(ty * 8 + i) * 4096 + tx * 8;
        *reinterpret_cast<float4*>(crow)     = c0;
        *reinterpret_cast<float4*>(crow + 4) = c1;
    }
}

// ---------------------------------------------------------------------------
// q softmax over dh (32 values strided by NPIX), then * dh^-0.5.
// one thread per (b,h,p) column.
// ---------------------------------------------------------------------------
__global__ __launch_bounds__(256) void qsoftmax_kernel()
{
    const int idx = blockIdx.x * 256 + threadIdx.x;   // 16*8*4096
    const int p = idx & 4095;
    const int h = (idx >> 12) & 7;
    const int b = idx >> 15;
    float* base = g_qkv + (long)b * QKV_ROWS * NPIX + (long)(h * DH) * NPIX + p;

    float v[DH];
    float m = -1e30f;
    #pragma unroll
    for (int d = 0; d < DH; ++d) {
        v[d] = base[(long)d * NPIX];
        m = fmaxf(m, v[d]);
    }
    float s = 0.f;
    #pragma unroll
    for (int d = 0; d < DH; ++d) {
        v[d] = expf(v[d] - m);
        s += v[d];
    }
    const float inv = 0.1767766952966369f / s;  // dh^-0.5 / sum
    #pragma unroll
    for (int d = 0; d < DH; ++d)
        base[(long)d * NPIX] = v[d] * inv;
}

// ---------------------------------------------------------------------------
// k softmax over n (4096 contiguous). One block per (b, h*32+d) row.
// ---------------------------------------------------------------------------
__global__ __launch_bounds__(256) void ksoftmax_kernel()
{
    const int row = blockIdx.x;         // 16*256
    const int b = row >> 8;
    const int c = row & 255;
    float* base = g_qkv + (long)b * QKV_ROWS * NPIX + (long)(256 + c) * NPIX;

    __shared__ float sm[NPIX];
    __shared__ float red[256];
    const int tid = threadIdx.x;

    float m = -1e30f;
    for (int i = tid; i < NPIX; i += 256) {
        float t = base[i];
        sm[i] = t;
        m = fmaxf(m, t);
    }
    red[tid] = m;
    __syncthreads();
    for (int s = 128; s > 0; s >>= 1) {
        if (tid < s) red[tid] = fmaxf(red[tid], red[tid + s]);
        __syncthreads();
    }
    m = red[0];
    __syncthreads();

    float sum = 0.f;
    for (int i = tid; i < NPIX; i += 256) {
        float e = expf(sm[i] - m);
        sm[i] = e;
        sum += e;
    }
    red[tid] = sum;
    __syncthreads();
    for (int s = 128; s > 0; s >>= 1) {
        if (tid < s) red[tid] += red[tid + s];
        __syncthreads();
    }
    const float inv = 1.f / red[0];
    __syncthreads();

    for (int i = tid; i < NPIX; i += 256)
        base[i] = sm[i] * inv;
}

// ---------------------------------------------------------------------------
// context[b,h,d,e] = (1/n) * sum_p k[d,p]*v[e,p]. One block per (b,h).
// ---------------------------------------------------------------------------
__global__ __launch_bounds__(256) void context_kernel()
{
    const int bh = blockIdx.x;          // 128
    const int b = bh >> 3;
    const int h = bh & 7;
    const float* kbase = g_qkv + (long)b * QKV_ROWS * NPIX + (long)(256 + h * DH) * NPIX;
    const float* vbase = g_qkv + (long)b * QKV_ROWS * NPIX + (long)(512 + h * DH) * NPIX;

    __shared__ float ks[DH][129];
    __shared__ float vs[DH][129];

    const int tid = threadIdx.x;
    const int d  = tid >> 3;           // 0..31
    const int e0 = (tid & 7) * 4;      // 0..28

    float acc[4] = {0.f, 0.f, 0.f, 0.f};

    for (int pc = 0; pc < NPIX; pc += 128) {
        __syncthreads();
        #pragma unroll
        for (int i = 0; i < 4; ++i) {
            int f4 = tid + i * 256;     // 0..1023 float4 slots
            int r  = f4 >> 5;
            int c4 = (f4 & 31) << 2;
            float4 kv = *reinterpret_cast<const float4*>(kbase + (long)r * NPIX + pc + c4);
            float4 vv = *reinterpret_cast<const float4*>(vbase + (long)r * NPIX + pc + c4);
            ks[r][c4] = kv.x; ks[r][c4+1] = kv.y; ks[r][c4+2] = kv.z; ks[r][c4+3] = kv.w;
            vs[r][c4] = vv.x; vs[r][c4+1] = vv.y; vs[r][c4+2] = vv.z; vs[r][c4+3] = vv.w;
        }
        __syncthreads();
        #pragma unroll 4
        for (int pp = 0; pp < 128; ++pp) {
            float kd = ks[d][pp];
            acc[0] += kd * vs[e0 + 0][pp];
            acc[1] += kd * vs[e0 + 1][pp];
            acc[2] += kd * vs[e0 + 2][pp];
            acc[3] += kd * vs[e0 + 3][pp];
        }
    }

    const float invn = 1.f / (float)NPIX;
    #pragma unroll
    for (int j = 0; j < 4; ++j)
        g_ctx[((long)bh * DH + d) * DH + e0 + j] = acc[j] * invn;
}

// ---------------------------------------------------------------------------
// M_b[o, h*32+d] = sum_e w_out[o, h*32+e] * ctx[b,h,d,e]. One block per (b,h).
// ---------------------------------------------------------------------------
__global__ __launch_bounds__(256) void buildM_kernel(const float* __restrict__ wout)
{
    const int bh = blockIdx.x;
    const int b = bh >> 3;
    const int h = bh & 7;

    __shared__ float cs[DH][DH + 1];
    const int tid = threadIdx.x;

    for (int i = tid; i < DH * DH; i += 256)
        cs[i >> 5][i & 31] = g_ctx[(long)bh * DH * DH + i];
    __syncthreads();

    float w[DH];
    const float* wr = wout + (long)tid * 256 + h * DH;
    #pragma unroll
    for (int e = 0; e < DH; ++e) w[e] = wr[e];

    float* mrow = g_M + (long)b * 65536 + (long)tid * 256 + h * DH;
    for (int d = 0; d < DH; ++d) {
        float s = 0.f;
        #pragma unroll
        for (int e = 0; e < DH; ++e) s += w[e] * cs[d][e];
        mrow[d] = s;
    }
}

// ---------------------------------------------------------------------------
// LayerNorm over C=256 per (b,p), with bias folded in. One thread per column.
// ---------------------------------------------------------------------------
__global__ __launch_bounds__(256) void layernorm_kernel(
    const float* __restrict__ bout, const float* __restrict__ gam,
    float* __restrict__ out)
{
    const int idx = blockIdx.x * 256 + threadIdx.x;   // 16*4096
    const int p = idx & 4095;
    const int b = idx >> 12;
    const float* base = g_y + (long)b * HID * NPIX + p;

    float sum = 0.f, sq = 0.f;
    for (int c = 0; c < HID; ++c) {
        float v = base[(long)c * NPIX] + bout[c];
        sum += v;
        sq  += v * v;
    }
    const float mean = sum * (1.f / 256.f);
    const float var  = sq * (1.f / 256.f) - mean * mean;
    const float inv  = rsqrtf(var + 1e-5f);

    float* obase = out + (long)b * HID * NPIX + p;
    for (int c = 0; c < HID; ++c) {
        float v = base[(long)c * NPIX] + bout[c];
        obase[(long)c * NPIX] = (v - mean) * inv * gam[c];
    }
}

// ---------------------------------------------------------------------------
extern "C" void kernel_launch(void* const* d_in, const int* in_sizes, int n_in,
                              void* d_out, int out_size)
{
    (void)in_sizes; (void)n_in; (void)out_size;
    const float* x     = (const float*)d_in[0];   // (16,256,64,64)
    const float* w_qkv = (const float*)d_in[1];   // (768,256)
    const float* w_out = (const float*)d_in[2];   // (256,256)
    const float* b_out = (const float*)d_in[3];   // (256,)
    const float* g     = (const float*)d_in[4];   // (256,)
    float* out = (float*)d_out;

    float *p_qkv = nullptr, *p_y = nullptr, *p_M = nullptr;
    cudaGetSymbolAddress((void**)&p_qkv, g_qkv);
    cudaGetSymbolAddress((void**)&p_y,   g_y);
    cudaGetSymbolAddress((void**)&p_M,   g_M);

    // 1. QKV GEMM: qkv_b = w_qkv @ x_b
    sgemm128<<<dim3(32, 6, BATCH), 256>>>(
        w_qkv, x, p_qkv,
        0L, (long)C_IN * NPIX, (long)QKV_ROWS * NPIX);

    // 2. q softmax over dh (+ scale)
    qsoftmax_kernel<<<(BATCH * HEADS * NPIX) / 256, 256>>>();

    // 3. k softmax over n
    ksoftmax_kernel<<<BATCH * HID, 256>>>();

    // 4. context = (k @ v^T) / n
    context_kernel<<<BATCH * HEADS, 256>>>();

    // 5. M_b = w_out folded with per-head context
    buildM_kernel<<<BATCH * HEADS, 256>>>(w_out);

    // 6. y_b = M_b @ q_b   (q = rows [0,256) of qkv_b)
    sgemm128<<<dim3(32, 2, BATCH), 256>>>(
        p_M, p_qkv, p_y,
        (long)HID * HID, (long)QKV_ROWS * NPIX, (long)HID * NPIX);

    // 7. LayerNorm(y + b_out) * g  -> d_out
    layernorm_kernel<<<(BATCH * NPIX) / 256, 256>>>(b_out, g, out);
}

// round 3
// speedup vs baseline: 1.6961x; 1.6961x over previous
#include <cuda_runtime.h>
#include <cuda_bf16.h>
#include <stdint.h>

#define BATCH   16
#define C_IN    256
#define HID     256
#define HEADS   8
#define DH      32
#define NPIX    4096
#define QKV_ROWS 768
#define KP      768          // split K' = 3*256
#define NCHUNK  12           // K' / 64

// ---------------- device scratch (no allocation allowed) -------------------
__device__ float g_qkv[BATCH * QKV_ROWS * NPIX];            // 192 MB fp32 qkv
__device__ __nv_bfloat16 g_Wsplit[QKV_ROWS * KP];           // W' [768,768]
__device__ __nv_bfloat16 g_Bsplit[BATCH * NPIX * KP];       // B' [b,4096,768]
__device__ __nv_bfloat16 g_A2[BATCH * HID * KP];            // M' [b,256,768]
__device__ float g_ctxp[BATCH * HEADS * 4 * DH * DH];       // context partials
__device__ float g_y  [BATCH * HID * NPIX];                 // 64 MB

// ---------------- PTX helpers (all base-ISA, no 'a'-suffix features) -------
__device__ __forceinline__ uint32_t smem_u32(const void* p) {
    uint32_t a;
    asm("{ .reg .u64 t; cvta.to.shared.u64 t, %1; cvt.u32.u64 %0, t; }" : "=r"(a) : "l"(p));
    return a;
}
__device__ __forceinline__ void cp16(uint32_t saddr, const void* gaddr) {
    asm volatile("cp.async.cg.shared.global [%0], [%1], 16;" :: "r"(saddr), "l"(gaddr) : "memory");
}
__device__ __forceinline__ void cp_commit() {
    asm volatile("cp.async.commit_group;" ::: "memory");
}
template <int N>
__device__ __forceinline__ void cp_wait() {
    asm volatile("cp.async.wait_group %0;" :: "n"(N) : "memory");
}
__device__ __forceinline__ void ldsm_x4(uint32_t* r, uint32_t addr) {
    asm volatile("ldmatrix.sync.aligned.m8n8.x4.shared.b16 {%0,%1,%2,%3}, [%4];"
                 : "=r"(r[0]), "=r"(r[1]), "=r"(r[2]), "=r"(r[3]) : "r"(addr));
}
__device__ __forceinline__ void ldsm_x2(uint32_t* r, uint32_t addr) {
    asm volatile("ldmatrix.sync.aligned.m8n8.x2.shared.b16 {%0,%1}, [%2];"
                 : "=r"(r[0]), "=r"(r[1]) : "r"(addr));
}
__device__ __forceinline__ void mma16816(float* c, const uint32_t* a, const uint32_t* b) {
    asm volatile(
        "mma.sync.aligned.m16n8k16.row.col.f32.bf16.bf16.f32 "
        "{%0,%1,%2,%3}, {%4,%5,%6,%7}, {%8,%9}, {%0,%1,%2,%3};"
        : "+f"(c[0]), "+f"(c[1]), "+f"(c[2]), "+f"(c[3])
        : "r"(a[0]), "r"(a[1]), "r"(a[2]), "r"(a[3]), "r"(b[0]), "r"(b[1]));
}

// ---------------------------------------------------------------------------
// bf16 HMMA GEMM:  C[M,4096] = A'[M,768] * B'[4096,768]^T  (per batch)
// CTA tile 128x128, 8 warps (warp tile 64x32), BK=64, 2-stage cp.async.
// SMEM rows padded to 144B -> conflict-free ldmatrix / STS.
// ---------------------------------------------------------------------------
#define LDS_B 144
#define OP_BYTES (128 * LDS_B)          // 18432 per operand per stage
#define STG_BYTES (2 * OP_BYTES)        // 36864 per stage

__global__ __launch_bounds__(256, 2) void gemm_mma(
    const __nv_bfloat16* __restrict__ A, const __nv_bfloat16* __restrict__ B,
    float* __restrict__ C, long aBatch, long bBatch, long cBatch)
{
    extern __shared__ char smem[];
    const uint32_t sb = smem_u32(smem);
    const int tid = threadIdx.x;
    const int wid = tid >> 5;
    const int lane = tid & 31;

    const char* Ab = (const char*)(A + blockIdx.z * aBatch + (long)blockIdx.x * 128 * KP);
    const char* Bb = (const char*)(B + blockIdx.z * bBatch + (long)blockIdx.y * 128 * KP);
    float* Cb = C + blockIdx.z * cBatch + (long)blockIdx.x * 128 * 4096 + blockIdx.y * 128;

    const int wm = (wid >> 2) * 64;     // warp row offset in tile
    const int wn = (wid & 3) * 32;      // warp col offset in tile

    float acc[4][4][4];
    #pragma unroll
    for (int i = 0; i < 4; ++i)
        #pragma unroll
        for (int j = 0; j < 4; ++j)
            #pragma unroll
            for (int k = 0; k < 4; ++k) acc[i][j][k] = 0.f;

    // ---- async copy of one K-chunk (64 bf16 = 128B per row) into stage s --
    const int r_ld = tid >> 3;              // base row for this thread (0..31)
    const int c16 = (tid & 7) * 16;         // 16B column within the 128B chunk
    auto cp_chunk = [&](int c, int s) {
        const long kbyte = (long)c * 128;
        const uint32_t as = sb + s * STG_BYTES;
        const uint32_t bs = as + OP_BYTES;
        #pragma unroll
        for (int i = 0; i < 4; ++i) {
            const int r = r_ld + i * 32;
            const uint32_t so = r * LDS_B + c16;
            cp16(as + so, Ab + (long)r * (KP * 2) + kbyte + c16);
            cp16(bs + so, Bb + (long)r * (KP * 2) + kbyte + c16);
        }
        cp_commit();
    };

    // ---- ldmatrix address lanes (constant per thread) ---------------------
    const int a_row = lane & 15;            // m row within 16
    const int a_koff = (lane >> 4) * 16;    // 0 / 16 bytes
    const int b_row = lane & 7;             // n row within 8
    const int b_koff = ((lane >> 3) & 1) * 16;

    cp_chunk(0, 0);

    for (int c = 0; c < NCHUNK; ++c) {
        const int s = c & 1;
        if (c + 1 < NCHUNK) cp_chunk(c + 1, s ^ 1);
        if (c + 1 < NCHUNK) cp_wait<1>(); else cp_wait<0>();
        __syncthreads();

        const uint32_t as = sb + s * STG_BYTES;
        const uint32_t bs = as + OP_BYTES;

        #pragma unroll
        for (int ks = 0; ks < 4; ++ks) {
            uint32_t afr[4][4], bfr[4][2];
            #pragma unroll
            for (int mt = 0; mt < 4; ++mt)
                ldsm_x4(afr[mt], as + (wm + mt * 16 + a_row) * LDS_B + ks * 32 + a_koff);
            #pragma unroll
            for (int nt = 0; nt < 4; ++nt)
                ldsm_x2(bfr[nt], bs + (wn + nt * 8 + b_row) * LDS_B + ks * 32 + b_koff);
            #pragma unroll
            for (int mt = 0; mt < 4; ++mt)
                #pragma unroll
                for (int nt = 0; nt < 4; ++nt)
                    mma16816(acc[mt][nt], afr[mt], bfr[nt]);
        }
        __syncthreads();
    }

    // ---- epilogue: fragment -> gmem fp32 ----------------------------------
    const int er = lane >> 2;           // 0..7
    const int ec = (lane & 3) * 2;      // 0,2,4,6
    #pragma unroll
    for (int mt = 0; mt < 4; ++mt) {
        #pragma unroll
        for (int nt = 0; nt < 4; ++nt) {
            float* p0 = Cb + (long)(wm + mt * 16 + er) * 4096 + wn + nt * 8 + ec;
            float* p1 = p0 + 8L * 4096;
            *reinterpret_cast<float2*>(p0) = make_float2(acc[mt][nt][0], acc[mt][nt][1]);
            *reinterpret_cast<float2*>(p1) = make_float2(acc[mt][nt][2], acc[mt][nt][3]);
        }
    }
}

// ---------------------------------------------------------------------------
// W split:  W'[m, 0:256)=hi, [256:512)=lo, [512:768)=hi   (A triple [Ah|Al|Ah])
// ---------------------------------------------------------------------------
__global__ __launch_bounds__(256) void conv_w_kernel(const float* __restrict__ w)
{
    const int m = blockIdx.x, c = threadIdx.x;
    const float v = w[m * 256 + c];
    const __nv_bfloat16 h = __float2bfloat16(v);
    const __nv_bfloat16 l = __float2bfloat16(v - __bfloat162float(h));
    __nv_bfloat16* o = g_Wsplit + (long)m * KP;
    o[c] = h; o[256 + c] = l; o[512 + c] = h;
}

// ---------------------------------------------------------------------------
// x transpose+split: x[b,c,p] -> B'[b,p, 0:256)=hi, [256:512)=hi, [512:768)=lo
// ---------------------------------------------------------------------------
__global__ __launch_bounds__(256) void transpose_split_x(const float* __restrict__ x)
{
    __shared__ float sm[32][129];
    const int b = blockIdx.z, c0 = blockIdx.y * 32, p0 = blockIdx.x * 128;
    const float* xb = x + ((long)b * 256 + c0) * 4096 + p0;
    const int tid = threadIdx.x;

    #pragma unroll
    for (int i = 0; i < 16; ++i) {
        const int u = tid + i * 256;
        sm[u >> 7][u & 127] = xb[(long)(u >> 7) * 4096 + (u & 127)];
    }
    __syncthreads();

    const int rr = tid >> 1, j0 = (tid & 1) * 16;
    __align__(16) __nv_bfloat16 hi[16], lo[16];
    #pragma unroll
    for (int j = 0; j < 16; ++j) {
        const float v = sm[j0 + j][rr];
        const __nv_bfloat16 h = __float2bfloat16(v);
        hi[j] = h;
        lo[j] = __float2bfloat16(v - __bfloat162float(h));
    }
    __nv_bfloat16* ob = g_Bsplit + ((long)b * NPIX + p0 + rr) * KP + c0 + j0;
    const uint4* hv = reinterpret_cast<const uint4*>(hi);
    const uint4* lv = reinterpret_cast<const uint4*>(lo);
    reinterpret_cast<uint4*>(ob)[0] = hv[0];
    reinterpret_cast<uint4*>(ob)[1] = hv[1];
    reinterpret_cast<uint4*>(ob + 256)[0] = hv[0];
    reinterpret_cast<uint4*>(ob + 256)[1] = hv[1];
    reinterpret_cast<uint4*>(ob + 512)[0] = lv[0];
    reinterpret_cast<uint4*>(ob + 512)[1] = lv[1];
}

// ---------------------------------------------------------------------------
// q softmax over dh (+scale), emit split-transposed into g_Bsplit [b,p,768]
// ---------------------------------------------------------------------------
__global__ __launch_bounds__(256) void qsoftmax_kernel()
{
    const int idx = blockIdx.x * 256 + threadIdx.x;
    const int p = idx & 4095;
    const int h = (idx >> 12) & 7;
    const int b = idx >> 15;
    const float* base = g_qkv + (long)b * QKV_ROWS * NPIX + (long)(h * DH) * NPIX + p;

    float v[DH];
    float m = -1e30f;
    #pragma unroll
    for (int d = 0; d < DH; ++d) { v[d] = base[(long)d * NPIX]; m = fmaxf(m, v[d]); }
    float s = 0.f;
    #pragma unroll
    for (int d = 0; d < DH; ++d) { v[d] = expf(v[d] - m); s += v[d]; }
    const float inv = 0.1767766952966369f / s;   // dh^-0.5 / sum

    __align__(16) __nv_bfloat16 hi[DH], lo[DH];
    #pragma unroll
    for (int d = 0; d < DH; ++d) {
        const float q = v[d] * inv;
        const __nv_bfloat16 hh = __float2bfloat16(q);
        hi[d] = hh;
        lo[d] = __float2bfloat16(q - __bfloat162float(hh));
    }
    __nv_bfloat16* ob = g_Bsplit + ((long)b * NPIX + p) * KP + h * DH;
    const uint4* hv = reinterpret_cast<const uint4*>(hi);
    const uint4* lv = reinterpret_cast<const uint4*>(lo);
    #pragma unroll
    for (int i = 0; i < 4; ++i) {
        reinterpret_cast<uint4*>(ob)[i] = hv[i];
        reinterpret_cast<uint4*>(ob + 256)[i] = hv[i];
        reinterpret_cast<uint4*>(ob + 512)[i] = lv[i];
    }
}

// ---------------------------------------------------------------------------
// k softmax over n (4096), fp32 inplace on g_qkv rows [256,512)
// ---------------------------------------------------------------------------
__global__ __launch_bounds__(256) void ksoftmax_kernel()
{
    const int row = blockIdx.x;
    const int b = row >> 8;
    const int c = row & 255;
    float* base = g_qkv + (long)b * QKV_ROWS * NPIX + (long)(256 + c) * NPIX;

    __shared__ float sm[NPIX];
    __shared__ float red[256];
    const int tid = threadIdx.x;

    float m = -1e30f;
    for (int i = tid; i < NPIX; i += 256) { float t = base[i]; sm[i] = t; m = fmaxf(m, t); }
    red[tid] = m; __syncthreads();
    for (int s = 128; s > 0; s >>= 1) { if (tid < s) red[tid] = fmaxf(red[tid], red[tid + s]); __syncthreads(); }
    m = red[0]; __syncthreads();

    float sum = 0.f;
    for (int i = tid; i < NPIX; i += 256) { float e = expf(sm[i] - m); sm[i] = e; sum += e; }
    red[tid] = sum; __syncthreads();
    for (int s = 128; s > 0; s >>= 1) { if (tid < s) red[tid] += red[tid + s]; __syncthreads(); }
    const float inv = 1.f / red[0]; __syncthreads();

    for (int i = tid; i < NPIX; i += 256) base[i] = sm[i] * inv;
}

// ---------------------------------------------------------------------------
// context partials: 4 pixel-chunks per (b,h). grid (128, 4)
// ---------------------------------------------------------------------------
__global__ __launch_bounds__(256) void context_kernel()
{
    const int bh = blockIdx.x;
    const int ch = blockIdx.y;
    const int b = bh >> 3, h = bh & 7;
    const float* kbase = g_qkv + (long)b * QKV_ROWS * NPIX + (long)(256 + h * DH) * NPIX + ch * 1024;
    const float* vbase = g_qkv + (long)b * QKV_ROWS * NPIX + (long)(512 + h * DH) * NPIX + ch * 1024;

    __shared__ float ks[DH][129];
    __shared__ float vs[DH][129];

    const int tid = threadIdx.x;
    const int d = tid >> 3;
    const int e0 = (tid & 7) * 4;

    float acc[4] = {0.f, 0.f, 0.f, 0.f};

    for (int pc = 0; pc < 1024; pc += 128) {
        __syncthreads();
        #pragma unroll
        for (int i = 0; i < 4; ++i) {
            const int f4 = tid + i * 256;
            const int r = f4 >> 5, c4 = (f4 & 31) << 2;
            const float4 kv = *reinterpret_cast<const float4*>(kbase + (long)r * NPIX + pc + c4);
            const float4 vv = *reinterpret_cast<const float4*>(vbase + (long)r * NPIX + pc + c4);
            ks[r][c4] = kv.x; ks[r][c4+1] = kv.y; ks[r][c4+2] = kv.z; ks[r][c4+3] = kv.w;
            vs[r][c4] = vv.x; vs[r][c4+1] = vv.y; vs[r][c4+2] = vv.z; vs[r][c4+3] = vv.w;
        }
        __syncthreads();
        #pragma unroll 4
        for (int pp = 0; pp < 128; ++pp) {
            const float kd = ks[d][pp];
            acc[0] += kd * vs[e0 + 0][pp];
            acc[1] += kd * vs[e0 + 1][pp];
            acc[2] += kd * vs[e0 + 2][pp];
            acc[3] += kd * vs[e0 + 3][pp];
        }
    }
    const float invn = 1.f / (float)NPIX;
    float* op = g_ctxp + ((long)bh * 4 + ch) * (DH * DH) + d * DH + e0;
    #pragma unroll
    for (int j = 0; j < 4; ++j) op[j] = acc[j] * invn;
}

// ---------------------------------------------------------------------------
// buildM: M[o, h*32+d] = sum_e wout[o,h*32+e] * ctx[d,e]; emit split A2 triple.
// ---------------------------------------------------------------------------
__global__ __launch_bounds__(256) void buildM_kernel(const float* __restrict__ wout)
{
    const int bh = blockIdx.x;
    const int b = bh >> 3, h = bh & 7;

    __shared__ float cs[DH][DH + 1];
    const int tid = threadIdx.x;

    for (int i = tid; i < DH * DH; i += 256) {
        float s = 0.f;
        #pragma unroll
        for (int ch = 0; ch < 4; ++ch)
            s += g_ctxp[((long)bh * 4 + ch) * (DH * DH) + i];
        cs[i >> 5][i & 31] = s;
    }
    __syncthreads();

    float w[DH];
    const float* wr = wout + (long)tid * 256 + h * DH;
    #pragma unroll
    for (int e = 0; e < DH; ++e) w[e] = wr[e];

    __align__(16) __nv_bfloat16 hi[DH], lo[DH];
    for (int d = 0; d < DH; ++d) {
        float s = 0.f;
        #pragma unroll
        for (int e = 0; e < DH; ++e) s += w[e] * cs[d][e];
        const __nv_bfloat16 hh = __float2bfloat16(s);
        hi[d] = hh;
        lo[d] = __float2bfloat16(s - __bfloat162float(hh));
    }
    __nv_bfloat16* ob = g_A2 + ((long)b * HID + tid) * KP + h * DH;
    const uint4* hv = reinterpret_cast<const uint4*>(hi);
    const uint4* lv = reinterpret_cast<const uint4*>(lo);
    #pragma unroll
    for (int i = 0; i < 4; ++i) {
        reinterpret_cast<uint4*>(ob)[i] = hv[i];          // seg0: hi
        reinterpret_cast<uint4*>(ob + 256)[i] = lv[i];    // seg1: lo
        reinterpret_cast<uint4*>(ob + 512)[i] = hv[i];    // seg2: hi
    }
}

// ---------------------------------------------------------------------------
// LayerNorm over C=256 per (b,p), bias folded.
// ---------------------------------------------------------------------------
__global__ __launch_bounds__(256) void layernorm_kernel(
    const float* __restrict__ bout, const float* __restrict__ gam,
    float* __restrict__ out)
{
    const int idx = blockIdx.x * 256 + threadIdx.x;
    const int p = idx & 4095;
    const int b = idx >> 12;
    const float* base = g_y + (long)b * HID * NPIX + p;

    float sum = 0.f, sq = 0.f;
    for (int c = 0; c < HID; ++c) {
        const float v = base[(long)c * NPIX] + bout[c];
        sum += v; sq += v * v;
    }
    const float mean = sum * (1.f / 256.f);
    const float var = sq * (1.f / 256.f) - mean * mean;
    const float inv = rsqrtf(var + 1e-5f);

    float* obase = out + (long)b * HID * NPIX + p;
    for (int c = 0; c < HID; ++c) {
        const float v = base[(long)c * NPIX] + bout[c];
        obase[(long)c * NPIX] = (v - mean) * inv * gam[c];
    }
}

// ---------------------------------------------------------------------------
extern "C" void kernel_launch(void* const* d_in, const int* in_sizes, int n_in,
                              void* d_out, int out_size)
{
    (void)in_sizes; (void)n_in; (void)out_size;
    const float* x     = (const float*)d_in[0];
    const float* w_qkv = (const float*)d_in[1];
    const float* w_out = (const float*)d_in[2];
    const float* b_out = (const float*)d_in[3];
    const float* g     = (const float*)d_in[4];
    float* out = (float*)d_out;

    float *p_qkv = nullptr, *p_y = nullptr;
    __nv_bfloat16 *p_W = nullptr, *p_B = nullptr, *p_A2 = nullptr;
    cudaGetSymbolAddress((void**)&p_qkv, g_qkv);
    cudaGetSymbolAddress((void**)&p_y,   g_y);
    cudaGetSymbolAddress((void**)&p_W,   g_Wsplit);
    cudaGetSymbolAddress((void**)&p_B,   g_Bsplit);
    cudaGetSymbolAddress((void**)&p_A2,  g_A2);

    const int SMEM_DYN = 2 * STG_BYTES;   // 73728 B
    cudaFuncSetAttribute(gemm_mma, cudaFuncAttributeMaxDynamicSharedMemorySize, SMEM_DYN);

    // 1. split weights / transpose+split activations
    conv_w_kernel<<<QKV_ROWS, 256>>>(w_qkv);
    transpose_split_x<<<dim3(32, 8, BATCH), 256>>>(x);

    // 2. QKV GEMM (HMMA): qkv[b] = W' * x'^T
    gemm_mma<<<dim3(6, 32, BATCH), 256, SMEM_DYN>>>(
        p_W, p_B, p_qkv, 0L, (long)NPIX * KP, (long)QKV_ROWS * NPIX);

    // 3. q softmax -> split q^T (overwrites g_Bsplit; gemm1 already consumed it)
    qsoftmax_kernel<<<(BATCH * HEADS * NPIX) / 256, 256>>>();

    // 4. k softmax
    ksoftmax_kernel<<<BATCH * HID, 256>>>();

    // 5. context partials + fold into M (split)
    context_kernel<<<dim3(BATCH * HEADS, 4), 256>>>();
    buildM_kernel<<<BATCH * HEADS, 256>>>(w_out);

    // 6. y[b] = M'[b] * q'^T (HMMA)
    gemm_mma<<<dim3(2, 32, BATCH), 256, SMEM_DYN>>>(
        p_A2, p_B, p_y, (long)HID * KP, (long)NPIX * KP, (long)HID * NPIX);

    // 7. LayerNorm
    layernorm_kernel<<<(BATCH * NPIX) / 256, 256>>>(b_out, g, out);
}

// round 4
// speedup vs baseline: 2.5691x; 1.5148x over previous
#include <cuda_runtime.h>
#include <cuda_fp16.h>
#include <stdint.h>

#define BATCH   16
#define HID     256
#define HEADS   8
#define DH      32
#define NPIX    4096
#define QKV_ROWS 768
#define KP      512          // fp16 2-term split K' = 2*256
#define NCHUNK  8            // K' / 64

// ---------------- device scratch ------------------------------------------
__device__ float g_qkv[BATCH * QKV_ROWS * NPIX];        // 192 MB fp32 qkv
__device__ __half g_W2[QKV_ROWS * KP];                  // [Wh|Wl] [768,512]
__device__ __half g_Bx[BATCH * 4 * NPIX * 64];          // chunk-major B (x^T then q^T), 32 MB
__device__ __half g_A2[BATCH * HID * KP];               // [Mh|Ml] [b,256,512]
__device__ float g_ctxp[BATCH * HEADS * 4 * DH * DH];   // context partials
__device__ float g_krow[BATCH * HID * 2];               // k-row (max, 1/sum)

// ---------------- PTX helpers (base ISA only) ------------------------------
__device__ __forceinline__ uint32_t smem_u32(const void* p) {
    uint32_t a;
    asm("{ .reg .u64 t; cvta.to.shared.u64 t, %1; cvt.u32.u64 %0, t; }" : "=r"(a) : "l"(p));
    return a;
}
__device__ __forceinline__ void cp16(uint32_t saddr, const void* gaddr) {
    asm volatile("cp.async.cg.shared.global [%0], [%1], 16;" :: "r"(saddr), "l"(gaddr) : "memory");
}
__device__ __forceinline__ void cp_commit() {
    asm volatile("cp.async.commit_group;" ::: "memory");
}
template <int N>
__device__ __forceinline__ void cp_wait() {
    asm volatile("cp.async.wait_group %0;" :: "n"(N) : "memory");
}
__device__ __forceinline__ void ldsm_x4(uint32_t* r, uint32_t addr) {
    asm volatile("ldmatrix.sync.aligned.m8n8.x4.shared.b16 {%0,%1,%2,%3}, [%4];"
                 : "=r"(r[0]), "=r"(r[1]), "=r"(r[2]), "=r"(r[3]) : "r"(addr));
}
__device__ __forceinline__ void ldsm_x2(uint32_t* r, uint32_t addr) {
    asm volatile("ldmatrix.sync.aligned.m8n8.x2.shared.b16 {%0,%1}, [%2];"
                 : "=r"(r[0]), "=r"(r[1]) : "r"(addr));
}
__device__ __forceinline__ void mma16816(float* c, const uint32_t* a, const uint32_t* b) {
    asm volatile(
        "mma.sync.aligned.m16n8k16.row.col.f32.f16.f16.f32 "
        "{%0,%1,%2,%3}, {%4,%5,%6,%7}, {%8,%9}, {%0,%1,%2,%3};"
        : "+f"(c[0]), "+f"(c[1]), "+f"(c[2]), "+f"(c[3])
        : "r"(a[0]), "r"(a[1]), "r"(a[2]), "r"(a[3]), "r"(b[0]), "r"(b[1]));
}

#define LDS_B 144

// ---------------------------------------------------------------------------
// GEMM1: C[768,4096] = A'[768,512] * Bx^T  (B chunk-major, wrap c&3)
// CTA 128x128, 8 warps (64x32 each), BK=64, 2-stage cp.async. fp32 out.
// ---------------------------------------------------------------------------
#define OP1 (128 * LDS_B)
#define STG1 (2 * OP1)

__global__ __launch_bounds__(256, 2) void gemm_mma(
    const __half* __restrict__ A, const __half* __restrict__ B,
    float* __restrict__ C)
{
    extern __shared__ char smem[];
    const uint32_t sb = smem_u32(smem);
    const int tid = threadIdx.x;
    const int wid = tid >> 5;
    const int lane = tid & 31;
    const int b = blockIdx.z;

    const char* Ab = (const char*)(A + (long)blockIdx.x * 128 * KP);
    const char* Bb = (const char*)B + ((long)b * 4 * NPIX + (long)blockIdx.y * 128) * 128;
    float* Cb = C + (long)b * QKV_ROWS * NPIX + (long)blockIdx.x * 128 * 4096 + blockIdx.y * 128;

    const int wm = (wid >> 2) * 64;
    const int wn = (wid & 3) * 32;

    float acc[4][4][4];
    #pragma unroll
    for (int i = 0; i < 4; ++i)
        #pragma unroll
        for (int j = 0; j < 4; ++j)
            #pragma unroll
            for (int k = 0; k < 4; ++k) acc[i][j][k] = 0.f;

    const int r_ld = tid >> 3;
    const int c16 = (tid & 7) * 16;
    auto cp_chunk = [&](int c, int s) {
        const uint32_t as = sb + s * STG1;
        const uint32_t bs = as + OP1;
        const long akb = (long)c * 128;
        const long bko = (long)(c & 3) * NPIX * 128;
        #pragma unroll
        for (int i = 0; i < 4; ++i) {
            const int r = r_ld + i * 32;
            const uint32_t so = r * LDS_B + c16;
            cp16(as + so, Ab + (long)r * (KP * 2) + akb + c16);
            cp16(bs + so, Bb + bko + (long)r * 128 + c16);
        }
        cp_commit();
    };

    const int a_row = lane & 15;
    const int a_koff = (lane >> 4) * 16;
    const int b_row = lane & 7;
    const int b_koff = ((lane >> 3) & 1) * 16;

    cp_chunk(0, 0);

    for (int c = 0; c < NCHUNK; ++c) {
        const int s = c & 1;
        if (c + 1 < NCHUNK) cp_chunk(c + 1, s ^ 1);
        if (c + 1 < NCHUNK) cp_wait<1>(); else cp_wait<0>();
        __syncthreads();

        const uint32_t as = sb + s * STG1;
        const uint32_t bs = as + OP1;
        #pragma unroll
        for (int ks = 0; ks < 4; ++ks) {
            uint32_t afr[4][4], bfr[4][2];
            #pragma unroll
            for (int mt = 0; mt < 4; ++mt)
                ldsm_x4(afr[mt], as + (wm + mt * 16 + a_row) * LDS_B + ks * 32 + a_koff);
            #pragma unroll
            for (int nt = 0; nt < 4; ++nt)
                ldsm_x2(bfr[nt], bs + (wn + nt * 8 + b_row) * LDS_B + ks * 32 + b_koff);
            #pragma unroll
            for (int mt = 0; mt < 4; ++mt)
                #pragma unroll
                for (int nt = 0; nt < 4; ++nt)
                    mma16816(acc[mt][nt], afr[mt], bfr[nt]);
        }
        __syncthreads();
    }

    const int er = lane >> 2;
    const int ec = (lane & 3) * 2;
    #pragma unroll
    for (int mt = 0; mt < 4; ++mt)
        #pragma unroll
        for (int nt = 0; nt < 4; ++nt) {
            float* p0 = Cb + (long)(wm + mt * 16 + er) * 4096 + wn + nt * 8 + ec;
            *reinterpret_cast<float2*>(p0) = make_float2(acc[mt][nt][0], acc[mt][nt][1]);
            *reinterpret_cast<float2*>(p0 + 8L * 4096) = make_float2(acc[mt][nt][2], acc[mt][nt][3]);
        }
}

// ---------------------------------------------------------------------------
// GEMM2 + fused bias + LayerNorm. CTA tile 256x64 (all channels in one CTA).
// A = [Mh|Ml] [256,512]; B = q chunk-major; out written normalized.
// ---------------------------------------------------------------------------
#define A2_ST (256 * LDS_B)       // 36864
#define B2_ST (64 * LDS_B)        // 9216
#define STG2  (A2_ST + B2_ST)     // 46080 per stage

__global__ __launch_bounds__(256, 1) void gemm_ln(
    const __half* __restrict__ A, const __half* __restrict__ B,
    const float* __restrict__ bout, const float* __restrict__ gam,
    float* __restrict__ out)
{
    extern __shared__ char smem[];
    const uint32_t sb = smem_u32(smem);
    const int tid = threadIdx.x;
    const int wid = tid >> 5;
    const int lane = tid & 31;
    const int b = blockIdx.z;
    const int n0 = blockIdx.x * 64;

    const char* Ab = (const char*)(A + (long)b * HID * KP);
    const char* Bb = (const char*)B + ((long)b * 4 * NPIX + n0) * 128;
    float* Cb = out + (long)b * HID * NPIX + n0;

    const int wm = (wid >> 1) * 64;     // 4 row groups
    const int wn = (wid & 1) * 32;      // 2 col groups

    float acc[4][4][4];
    #pragma unroll
    for (int i = 0; i < 4; ++i)
        #pragma unroll
        for (int j = 0; j < 4; ++j)
            #pragma unroll
            for (int k = 0; k < 4; ++k) acc[i][j][k] = 0.f;

    const int r_ld = tid >> 3;
    const int c16 = (tid & 7) * 16;
    auto cp_chunk = [&](int c, int s) {
        const uint32_t as = sb + s * STG2;
        const uint32_t bs = as + A2_ST;
        const long akb = (long)c * 128;
        const long bko = (long)(c & 3) * NPIX * 128;
        #pragma unroll
        for (int i = 0; i < 8; ++i) {              // A: 256 rows
            const int r = r_ld + i * 32;
            cp16(as + r * LDS_B + c16, Ab + (long)r * (KP * 2) + akb + c16);
        }
        #pragma unroll
        for (int i = 0; i < 2; ++i) {              // B: 64 rows
            const int r = r_ld + i * 32;
            cp16(bs + r * LDS_B + c16, Bb + bko + (long)r * 128 + c16);
        }
        cp_commit();
    };

    const int a_row = lane & 15;
    const int a_koff = (lane >> 4) * 16;
    const int b_row = lane & 7;
    const int b_koff = ((lane >> 3) & 1) * 16;

    cp_chunk(0, 0);

    for (int c = 0; c < NCHUNK; ++c) {
        const int s = c & 1;
        if (c + 1 < NCHUNK) cp_chunk(c + 1, s ^ 1);
        if (c + 1 < NCHUNK) cp_wait<1>(); else cp_wait<0>();
        __syncthreads();

        const uint32_t as = sb + s * STG2;
        const uint32_t bs = as + A2_ST;
        #pragma unroll
        for (int ks = 0; ks < 4; ++ks) {
            uint32_t afr[4][4], bfr[4][2];
            #pragma unroll
            for (int mt = 0; mt < 4; ++mt)
                ldsm_x4(afr[mt], as + (wm + mt * 16 + a_row) * LDS_B + ks * 32 + a_koff);
            #pragma unroll
            for (int nt = 0; nt < 4; ++nt)
                ldsm_x2(bfr[nt], bs + (wn + nt * 8 + b_row) * LDS_B + ks * 32 + b_koff);
            #pragma unroll
            for (int mt = 0; mt < 4; ++mt)
                #pragma unroll
                for (int nt = 0; nt < 4; ++nt)
                    mma16816(acc[mt][nt], afr[mt], bfr[nt]);
        }
        __syncthreads();
    }

    // ---- epilogue: bias + LayerNorm over the 256 rows ----------------------
    const int er = lane >> 2;
    const int ec = (lane & 3) * 2;

    float bo[8], ga[8];
    #pragma unroll
    for (int mt = 0; mt < 4; ++mt) {
        const int r0 = wm + mt * 16 + er;
        bo[mt * 2] = bout[r0];        bo[mt * 2 + 1] = bout[r0 + 8];
        ga[mt * 2] = gam[r0];         ga[mt * 2 + 1] = gam[r0 + 8];
    }

    float cs[4][2], cq[4][2];
    #pragma unroll
    for (int nt = 0; nt < 4; ++nt)
        #pragma unroll
        for (int par = 0; par < 2; ++par) {
            float s = 0.f, q = 0.f;
            #pragma unroll
            for (int mt = 0; mt < 4; ++mt) {
                float v0 = acc[mt][nt][par]     + bo[mt * 2];
                float v1 = acc[mt][nt][par + 2] + bo[mt * 2 + 1];
                acc[mt][nt][par] = v0;
                acc[mt][nt][par + 2] = v1;
                s += v0 + v1;
                q += v0 * v0 + v1 * v1;
            }
            cs[nt][par] = s;
            cq[nt][par] = q;
        }
    #pragma unroll
    for (int off = 4; off < 32; off <<= 1)
        #pragma unroll
        for (int nt = 0; nt < 4; ++nt)
            #pragma unroll
            for (int par = 0; par < 2; ++par) {
                cs[nt][par] += __shfl_xor_sync(0xFFFFFFFFu, cs[nt][par], off);
                cq[nt][par] += __shfl_xor_sync(0xFFFFFFFFu, cq[nt][par], off);
            }

    float* red = (float*)smem;          // [4 row-groups][64 cols][2]
    float2* lnp = (float2*)(smem + 2048);
    __syncthreads();                     // stages dead; reuse smem
    if (er == 0) {
        const int wr = wid >> 1;
        #pragma unroll
        for (int nt = 0; nt < 4; ++nt)
            #pragma unroll
            for (int par = 0; par < 2; ++par) {
                const int col = wn + nt * 8 + ec + par;
                red[(wr * 64 + col) * 2]     = cs[nt][par];
                red[(wr * 64 + col) * 2 + 1] = cq[nt][par];
            }
    }
    __syncthreads();
    if (tid < 64) {
        float s = 0.f, q = 0.f;
        #pragma unroll
        for (int wr = 0; wr < 4; ++wr) {
            s += red[(wr * 64 + tid) * 2];
            q += red[(wr * 64 + tid) * 2 + 1];
        }
        const float mean = s * (1.f / 256.f);
        const float var = q * (1.f / 256.f) - mean * mean;
        lnp[tid] = make_float2(mean, rsqrtf(var + 1e-5f));
    }
    __syncthreads();

    #pragma unroll
    for (int mt = 0; mt < 4; ++mt)
        #pragma unroll
        for (int nt = 0; nt < 4; ++nt) {
            const float2 l0 = lnp[wn + nt * 8 + ec];
            const float2 l1 = lnp[wn + nt * 8 + ec + 1];
            float* p0 = Cb + (long)(wm + mt * 16 + er) * 4096 + wn + nt * 8 + ec;
            *reinterpret_cast<float2*>(p0) = make_float2(
                (acc[mt][nt][0] - l0.x) * l0.y * ga[mt * 2],
                (acc[mt][nt][1] - l1.x) * l1.y * ga[mt * 2]);
            *reinterpret_cast<float2*>(p0 + 8L * 4096) = make_float2(
                (acc[mt][nt][2] - l0.x) * l0.y * ga[mt * 2 + 1],
                (acc[mt][nt][3] - l1.x) * l1.y * ga[mt * 2 + 1]);
        }
}

// ---------------------------------------------------------------------------
// W split (fp16 hi/lo): W2[m, 0:256)=hi, [256:512)=lo
// ---------------------------------------------------------------------------
__global__ __launch_bounds__(256) void conv_w_kernel(const float* __restrict__ w)
{
    const int m = blockIdx.x, c = threadIdx.x;
    const float v = w[m * 256 + c];
    const __half h = __float2half(v);
    g_W2[(long)m * KP + c] = h;
    g_W2[(long)m * KP + 256 + c] = __float2half(v - __half2float(h));
}

// ---------------------------------------------------------------------------
// x transpose (hi only) into chunk-major g_Bx[b][c/64][p][64]
// ---------------------------------------------------------------------------
__global__ __launch_bounds__(256) void transpose_x(const float* __restrict__ x, int zoff)
{
    __shared__ float sm[32][129];
    const int b = blockIdx.z + zoff, c0 = blockIdx.y * 32, p0 = blockIdx.x * 128;
    const float* xb = x + ((long)b * 256 + c0) * 4096 + p0;
    const int tid = threadIdx.x;

    #pragma unroll
    for (int i = 0; i < 16; ++i) {
        const int u = tid + i * 256;
        sm[u >> 7][u & 127] = xb[(long)(u >> 7) * 4096 + (u & 127)];
    }
    __syncthreads();

    const int rr = tid >> 1, j0 = (tid & 1) * 16;
    __align__(16) __half hv[16];
    #pragma unroll
    for (int j = 0; j < 16; ++j) hv[j] = __float2half(sm[j0 + j][rr]);

    __half* ob = g_Bx + (((long)b * 4 + (c0 >> 6)) * NPIX + p0 + rr) * 64 + (c0 & 63) + j0;
    reinterpret_cast<uint4*>(ob)[0] = reinterpret_cast<const uint4*>(hv)[0];
    reinterpret_cast<uint4*>(ob)[1] = reinterpret_cast<const uint4*>(hv)[1];
}

// ---------------------------------------------------------------------------
// q softmax (head pair per thread) -> g_Bx chunk-major, 128B coalesced writes
// ---------------------------------------------------------------------------
__global__ __launch_bounds__(256) void qsoftmax_kernel()
{
    const int idx = blockIdx.x * 256 + threadIdx.x;     // 16*4*4096
    const int p = idx & 4095;
    const int hp = (idx >> 12) & 3;
    const int b = idx >> 14;
    const float* qb = g_qkv + (long)b * QKV_ROWS * NPIX + (long)hp * 64 * 4096 + p;

    float v[64];
    __align__(16) __half o[64];
    #pragma unroll
    for (int h2 = 0; h2 < 2; ++h2) {
        float m = -1e30f;
        #pragma unroll
        for (int d = 0; d < 32; ++d) {
            v[h2 * 32 + d] = qb[(long)(h2 * 32 + d) * 4096];
            m = fmaxf(m, v[h2 * 32 + d]);
        }
        float s = 0.f;
        #pragma unroll
        for (int d = 0; d < 32; ++d) {
            v[h2 * 32 + d] = expf(v[h2 * 32 + d] - m);
            s += v[h2 * 32 + d];
        }
        const float inv = 0.1767766952966369f / s;
        #pragma unroll
        for (int d = 0; d < 32; ++d)
            o[h2 * 32 + d] = __float2half(v[h2 * 32 + d] * inv);
    }
    __half* ob = g_Bx + (((long)b * 4 + hp) * NPIX + p) * 64;
    #pragma unroll
    for (int i = 0; i < 8; ++i)
        reinterpret_cast<uint4*>(ob)[i] = reinterpret_cast<const uint4*>(o)[i];
}

// ---------------------------------------------------------------------------
// k row reduce: per (b,c) row of k, compute (max, 1/sum_exp)
// ---------------------------------------------------------------------------
__global__ __launch_bounds__(256) void kreduce_kernel()
{
    const int row = blockIdx.x;              // 16*256
    const int b = row >> 8, c = row & 255;
    const float* base = g_qkv + (long)b * QKV_ROWS * NPIX + (long)(256 + c) * 4096;
    const int tid = threadIdx.x;

    __shared__ float red[256];
    float vl[16];
    float m = -1e30f;
    #pragma unroll
    for (int i = 0; i < 16; ++i) { vl[i] = base[tid + i * 256]; m = fmaxf(m, vl[i]); }
    red[tid] = m; __syncthreads();
    for (int s = 128; s > 0; s >>= 1) { if (tid < s) red[tid] = fmaxf(red[tid], red[tid + s]); __syncthreads(); }
    m = red[0]; __syncthreads();
    float sum = 0.f;
    #pragma unroll
    for (int i = 0; i < 16; ++i) sum += expf(vl[i] - m);
    red[tid] = sum; __syncthreads();
    for (int s = 128; s > 0; s >>= 1) { if (tid < s) red[tid] += red[tid + s]; __syncthreads(); }
    if (tid == 0) {
        g_krow[row * 2] = m;
        g_krow[row * 2 + 1] = 1.f / red[0];
    }
}

// ---------------------------------------------------------------------------
// context partials with fused k-softmax normalization. grid (128, 4)
// ---------------------------------------------------------------------------
__global__ __launch_bounds__(256) void context_kernel()
{
    const int bh = blockIdx.x;
    const int ch = blockIdx.y;
    const int b = bh >> 3, h = bh & 7;
    const float* kbase = g_qkv + (long)b * QKV_ROWS * NPIX + (long)(256 + h * DH) * 4096 + ch * 1024;
    const float* vbase = g_qkv + (long)b * QKV_ROWS * NPIX + (long)(512 + h * DH) * 4096 + ch * 1024;

    __shared__ float ks[DH][129];
    __shared__ float vs[DH][129];
    __shared__ float km[DH], ki[DH];

    const int tid = threadIdx.x;
    if (tid < DH) {
        const int kr = b * 256 + h * DH + tid;
        km[tid] = g_krow[kr * 2];
        ki[tid] = g_krow[kr * 2 + 1];
    }
    __syncthreads();

    const int d = tid >> 3;
    const int e0 = (tid & 7) * 4;
    float acc[4] = {0.f, 0.f, 0.f, 0.f};

    for (int pc = 0; pc < 1024; pc += 128) {
        __syncthreads();
        #pragma unroll
        for (int i = 0; i < 4; ++i) {
            const int f4 = tid + i * 256;
            const int r = f4 >> 5, c4 = (f4 & 31) << 2;
            const float4 kv = *reinterpret_cast<const float4*>(kbase + (long)r * 4096 + pc + c4);
            const float4 vv = *reinterpret_cast<const float4*>(vbase + (long)r * 4096 + pc + c4);
            const float mm = km[r], ii = ki[r];
            ks[r][c4]   = expf(kv.x - mm) * ii;
            ks[r][c4+1] = expf(kv.y - mm) * ii;
            ks[r][c4+2] = expf(kv.z - mm) * ii;
            ks[r][c4+3] = expf(kv.w - mm) * ii;
            vs[r][c4] = vv.x; vs[r][c4+1] = vv.y; vs[r][c4+2] = vv.z; vs[r][c4+3] = vv.w;
        }
        __syncthreads();
        #pragma unroll 4
        for (int pp = 0; pp < 128; ++pp) {
            const float kd = ks[d][pp];
            acc[0] += kd * vs[e0 + 0][pp];
            acc[1] += kd * vs[e0 + 1][pp];
            acc[2] += kd * vs[e0 + 2][pp];
            acc[3] += kd * vs[e0 + 3][pp];
        }
    }
    const float invn = 1.f / (float)NPIX;
    float* op = g_ctxp + ((long)bh * 4 + ch) * (DH * DH) + d * DH + e0;
    #pragma unroll
    for (int j = 0; j < 4; ++j) op[j] = acc[j] * invn;
}

// ---------------------------------------------------------------------------
// buildM -> fp16 [Mh|Ml] in g_A2
// ---------------------------------------------------------------------------
__global__ __launch_bounds__(256) void buildM_kernel(const float* __restrict__ wout)
{
    const int bh = blockIdx.x;
    const int b = bh >> 3, h = bh & 7;

    __shared__ float cs[DH][DH + 1];
    const int tid = threadIdx.x;

    for (int i = tid; i < DH * DH; i += 256) {
        float s = 0.f;
        #pragma unroll
        for (int ch = 0; ch < 4; ++ch)
            s += g_ctxp[((long)bh * 4 + ch) * (DH * DH) + i];
        cs[i >> 5][i & 31] = s;
    }
    __syncthreads();

    float w[DH];
    const float* wr = wout + (long)tid * 256 + h * DH;
    #pragma unroll
    for (int e = 0; e < DH; ++e) w[e] = wr[e];

    __align__(16) __half hi[DH], lo[DH];
    for (int d = 0; d < DH; ++d) {
        float s = 0.f;
        #pragma unroll
        for (int e = 0; e < DH; ++e) s += w[e] * cs[d][e];
        const __half hh = __float2half(s);
        hi[d] = hh;
        lo[d] = __float2half(s - __half2float(hh));
    }
    __half* ob = g_A2 + ((long)b * HID + tid) * KP + h * DH;
    #pragma unroll
    for (int i = 0; i < 4; ++i) {
        reinterpret_cast<uint4*>(ob)[i] = reinterpret_cast<const uint4*>(hi)[i];
        reinterpret_cast<uint4*>(ob + 256)[i] = reinterpret_cast<const uint4*>(lo)[i];
    }
}

// ---------------------------------------------------------------------------
extern "C" void kernel_launch(void* const* d_in, const int* in_sizes, int n_in,
                              void* d_out, int out_size)
{
    (void)in_sizes; (void)n_in; (void)out_size;
    const float* x     = (const float*)d_in[0];
    const float* w_qkv = (const float*)d_in[1];
    const float* w_out = (const float*)d_in[2];
    const float* b_out = (const float*)d_in[3];
    const float* g     = (const float*)d_in[4];
    float* out = (float*)d_out;

    float* p_qkv = nullptr;
    __half *p_W = nullptr, *p_B = nullptr, *p_A2 = nullptr;
    cudaGetSymbolAddress((void**)&p_qkv, g_qkv);
    cudaGetSymbolAddress((void**)&p_W,   g_W2);
    cudaGetSymbolAddress((void**)&p_B,   g_Bx);
    cudaGetSymbolAddress((void**)&p_A2,  g_A2);

    cudaFuncSetAttribute(gemm_mma, cudaFuncAttributeMaxDynamicSharedMemorySize, 2 * STG1);
    cudaFuncSetAttribute(gemm_ln,  cudaFuncAttributeMaxDynamicSharedMemorySize, 2 * STG2);

    // launch 0..2: prep (keeps gemm1 at profiled slot 3)
    conv_w_kernel<<<QKV_ROWS, 256>>>(w_qkv);
    transpose_x<<<dim3(32, 8, 8), 256>>>(x, 0);
    transpose_x<<<dim3(32, 8, 8), 256>>>(x, 8);

    // 3: QKV GEMM (fp16 HMMA, 2-term split)
    gemm_mma<<<dim3(6, 32, BATCH), 256, 2 * STG1>>>(p_W, p_B, p_qkv);

    // 4: q softmax -> chunk-major q^T (overwrites g_Bx)
    qsoftmax_kernel<<<(BATCH * 4 * NPIX) / 256, 256>>>();

    // 5: k row reduce (max, 1/sum)
    kreduce_kernel<<<BATCH * HID, 256>>>();

    // 6: context partials (fused k normalization)
    context_kernel<<<dim3(BATCH * HEADS, 4), 256>>>();

    // 7: M fold -> fp16 split
    buildM_kernel<<<BATCH * HEADS, 256>>>(w_out);

    // 8: y GEMM + bias + LayerNorm -> d_out
    gemm_ln<<<dim3(64, 1, BATCH), 256, 2 * STG2>>>(p_A2, p_B, b_out, g, out);
}

// round 5
// speedup vs baseline: 2.6978x; 1.0501x over previous
#include <cuda_runtime.h>
#include <cuda_fp16.h>
#include <stdint.h>

#define BATCH   16
#define HID     256
#define HEADS   8
#define DH      32
#define NPIX    4096
#define QKV_ROWS 768
#define KP      512          // fp16 2-term split K' = 2*256
#define NCHUNK  8            // K' / 64

// ---------------- device scratch ------------------------------------------
__device__ float g_qkv[BATCH * QKV_ROWS * NPIX];        // k,v fp32 (q rows unused)
__device__ __half g_W2[QKV_ROWS * KP];                  // [Wh|Wl] [768,512]
__device__ __half g_Bx[BATCH * 4 * NPIX * 64];          // chunk-major x^T (hi), 32 MB
__device__ __half g_Bq[BATCH * 4 * NPIX * 64];          // chunk-major softmaxed q^T, 32 MB
__device__ __half g_A2[BATCH * HID * KP];               // [Mh|Ml] [b,256,512]
__device__ float g_ctxp[BATCH * HEADS * 4 * DH * DH];   // context partials
__device__ float2 g_kpart[BATCH * 256 * 32];            // k row partials (m, sumexp) per 128-col block

// ---------------- PTX helpers (base ISA only) ------------------------------
__device__ __forceinline__ uint32_t smem_u32(const void* p) {
    uint32_t a;
    asm("{ .reg .u64 t; cvta.to.shared.u64 t, %1; cvt.u32.u64 %0, t; }" : "=r"(a) : "l"(p));
    return a;
}
__device__ __forceinline__ void cp16(uint32_t saddr, const void* gaddr) {
    asm volatile("cp.async.cg.shared.global [%0], [%1], 16;" :: "r"(saddr), "l"(gaddr) : "memory");
}
__device__ __forceinline__ void cp_commit() {
    asm volatile("cp.async.commit_group;" ::: "memory");
}
template <int N>
__device__ __forceinline__ void cp_wait() {
    asm volatile("cp.async.wait_group %0;" :: "n"(N) : "memory");
}
__device__ __forceinline__ void ldsm_x4(uint32_t* r, uint32_t addr) {
    asm volatile("ldmatrix.sync.aligned.m8n8.x4.shared.b16 {%0,%1,%2,%3}, [%4];"
                 : "=r"(r[0]), "=r"(r[1]), "=r"(r[2]), "=r"(r[3]) : "r"(addr));
}
__device__ __forceinline__ void mma16816(float* c, const uint32_t* a, const uint32_t* b) {
    asm volatile(
        "mma.sync.aligned.m16n8k16.row.col.f32.f16.f16.f32 "
        "{%0,%1,%2,%3}, {%4,%5,%6,%7}, {%8,%9}, {%0,%1,%2,%3};"
        : "+f"(c[0]), "+f"(c[1]), "+f"(c[2]), "+f"(c[3])
        : "r"(a[0]), "r"(a[1]), "r"(a[2]), "r"(a[3]), "r"(b[0]), "r"(b[1]));
}

#define LDS_B 144
#define OP1 (128 * LDS_B)
#define STG1 (2 * OP1)           // 36864 per stage
#define SMEM1 (3 * STG1)         // 110592, 3 stages

// ---------------------------------------------------------------------------
// GEMM1 + fused q-softmax / k-partial epilogues.
// C row-block bx: 0-1 = q (softmax -> g_Bq fp16), 2-3 = k (fp32 + partials),
// 4-5 = v (fp32). CTA 128x128, 8 warps (64x32), BK=64, 3-stage cp.async.
// ---------------------------------------------------------------------------
__global__ __launch_bounds__(256, 2) void gemm_mma(
    const __half* __restrict__ A, const __half* __restrict__ B)
{
    extern __shared__ char smem[];
    const uint32_t sb = smem_u32(smem);
    const int tid = threadIdx.x;
    const int wid = tid >> 5;
    const int lane = tid & 31;
    const int bx = blockIdx.x, by = blockIdx.y, b = blockIdx.z;

    const char* Ab = (const char*)(A + (long)bx * 128 * KP);
    const char* Bb = (const char*)B + ((long)b * 4 * NPIX + (long)by * 128) * 128;

    const int wm = (wid >> 2) * 64;
    const int wn = (wid & 3) * 32;

    float acc[4][4][4];
    #pragma unroll
    for (int i = 0; i < 4; ++i)
        #pragma unroll
        for (int j = 0; j < 4; ++j)
            #pragma unroll
            for (int k = 0; k < 4; ++k) acc[i][j][k] = 0.f;

    const int r_ld = tid >> 3;
    const int c16 = (tid & 7) * 16;
    auto cp_chunk = [&](int c) {
        const uint32_t as = sb + (c % 3) * STG1;
        const uint32_t bs = as + OP1;
        const long akb = (long)c * 128;
        const long bko = (long)(c & 3) * NPIX * 128;
        #pragma unroll
        for (int i = 0; i < 4; ++i) {
            const int r = r_ld + i * 32;
            const uint32_t so = r * LDS_B + c16;
            cp16(as + so, Ab + (long)r * (KP * 2) + akb + c16);
            cp16(bs + so, Bb + bko + (long)r * 128 + c16);
        }
        cp_commit();
    };

    // ldmatrix lane addressing
    const int a_row = lane & 15;
    const int a_koff = (lane >> 4) * 16;
    const int b_row = lane & 7;
    const int b_n8 = (lane >> 4) * 8;
    const int b_koff = ((lane >> 3) & 1) * 16;

    cp_chunk(0);
    cp_chunk(1);

    for (int c = 0; c < NCHUNK; ++c) {
        if (c < NCHUNK - 1) cp_wait<1>(); else cp_wait<0>();
        __syncthreads();
        if (c + 2 < NCHUNK) cp_chunk(c + 2);

        const uint32_t as = sb + (c % 3) * STG1;
        const uint32_t bs = as + OP1;
        #pragma unroll
        for (int ks = 0; ks < 4; ++ks) {
            uint32_t afr[4][4], bfr[4][2];
            #pragma unroll
            for (int mt = 0; mt < 4; ++mt)
                ldsm_x4(afr[mt], as + (wm + mt * 16 + a_row) * LDS_B + ks * 32 + a_koff);
            #pragma unroll
            for (int np = 0; np < 2; ++np) {
                uint32_t bq[4];
                ldsm_x4(bq, bs + (wn + np * 16 + b_n8 + b_row) * LDS_B + ks * 32 + b_koff);
                bfr[np * 2][0] = bq[0]; bfr[np * 2][1] = bq[1];
                bfr[np * 2 + 1][0] = bq[2]; bfr[np * 2 + 1][1] = bq[3];
            }
            #pragma unroll
            for (int mt = 0; mt < 4; ++mt)
                #pragma unroll
                for (int nt = 0; nt < 4; ++nt)
                    mma16816(acc[mt][nt], afr[mt], bfr[nt]);
        }
    }

    const int er = lane >> 2;
    const int ec = (lane & 3) * 2;

    // ---- k,v rows: fp32 write to g_qkv -------------------------------------
    if (bx >= 2) {
        float* Cb = g_qkv + (long)b * QKV_ROWS * NPIX + (long)bx * 128 * 4096 + by * 128;
        #pragma unroll
        for (int mt = 0; mt < 4; ++mt)
            #pragma unroll
            for (int nt = 0; nt < 4; ++nt) {
                float* p0 = Cb + (long)(wm + mt * 16 + er) * 4096 + wn + nt * 8 + ec;
                *reinterpret_cast<float2*>(p0) = make_float2(acc[mt][nt][0], acc[mt][nt][1]);
                *reinterpret_cast<float2*>(p0 + 8L * 4096) = make_float2(acc[mt][nt][2], acc[mt][nt][3]);
            }
    }
    if (bx >= 4) return;   // v done

    // ---- stage acc tile into (now dead) smem as fp32 [128][129] ------------
    float* sfl = (float*)smem;
    __syncthreads();
    #pragma unroll
    for (int mt = 0; mt < 4; ++mt)
        #pragma unroll
        for (int nt = 0; nt < 4; ++nt) {
            const int r0 = wm + mt * 16 + er;
            const int c0 = wn + nt * 8 + ec;
            sfl[r0 * 129 + c0] = acc[mt][nt][0];
            sfl[r0 * 129 + c0 + 1] = acc[mt][nt][1];
            sfl[(r0 + 8) * 129 + c0] = acc[mt][nt][2];
            sfl[(r0 + 8) * 129 + c0 + 1] = acc[mt][nt][3];
        }
    __syncthreads();

    if (bx < 2) {
        // ---- q path: softmax over d (32 rows), scale, emit fp16 chunk-major
        #pragma unroll
        for (int t = tid; t < 512; t += 256) {
            const int hb = t >> 7;          // head within CTA (0..3)
            const int col = t & 127;
            float v[DH];
            float m = -1e30f;
            #pragma unroll
            for (int d = 0; d < DH; ++d) {
                v[d] = sfl[(hb * 32 + d) * 129 + col];
                m = fmaxf(m, v[d]);
            }
            float s = 0.f;
            #pragma unroll
            for (int d = 0; d < DH; ++d) { v[d] = expf(v[d] - m); s += v[d]; }
            const float inv = 0.1767766952966369f / s;
            __align__(16) __half o[DH];
            #pragma unroll
            for (int d = 0; d < DH; ++d) o[d] = __float2half(v[d] * inv);

            const int gh = bx * 4 + hb;
            const long gcol = (long)by * 128 + col;
            __half* ob = g_Bq + (((long)b * 4 + (gh >> 1)) * NPIX + gcol) * 64 + (gh & 1) * 32;
            #pragma unroll
            for (int i = 0; i < 4; ++i)
                reinterpret_cast<uint4*>(ob)[i] = reinterpret_cast<const uint4*>(o)[i];
        }
    } else {
        // ---- k path: per-row (max, sumexp) partial over this 128-col block
        const int row = tid >> 1;
        const int half = tid & 1;
        const float* rp = sfl + row * 129 + half * 64;
        float m = -1e30f;
        #pragma unroll
        for (int j = 0; j < 64; ++j) m = fmaxf(m, rp[j]);
        float s = 0.f;
        #pragma unroll
        for (int j = 0; j < 64; ++j) s += expf(rp[j] - m);
        const float mo = __shfl_xor_sync(0xFFFFFFFFu, m, 1);
        const float so = __shfl_xor_sync(0xFFFFFFFFu, s, 1);
        const float mg = fmaxf(m, mo);
        const float sg = s * expf(m - mg) + so * expf(mo - mg);
        if (half == 0) {
            const int krow = (bx - 2) * 128 + row;
            g_kpart[((long)b * 256 + krow) * 32 + by] = make_float2(mg, sg);
        }
    }
}

// ---------------------------------------------------------------------------
// GEMM2 + fused bias + LayerNorm. CTA tile 256x64. 2-stage cp.async.
// ---------------------------------------------------------------------------
#define A2_ST (256 * LDS_B)       // 36864
#define B2_ST (64 * LDS_B)        // 9216
#define STG2  (A2_ST + B2_ST)     // 46080 per stage

__global__ __launch_bounds__(256, 1) void gemm_ln(
    const __half* __restrict__ A, const __half* __restrict__ B,
    const float* __restrict__ bout, const float* __restrict__ gam,
    float* __restrict__ out)
{
    extern __shared__ char smem[];
    const uint32_t sb = smem_u32(smem);
    const int tid = threadIdx.x;
    const int wid = tid >> 5;
    const int lane = tid & 31;
    const int b = blockIdx.z;
    const int n0 = blockIdx.x * 64;

    const char* Ab = (const char*)(A + (long)b * HID * KP);
    const char* Bb = (const char*)B + ((long)b * 4 * NPIX + n0) * 128;
    float* Cb = out + (long)b * HID * NPIX + n0;

    const int wm = (wid >> 1) * 64;
    const int wn = (wid & 1) * 32;

    float acc[4][4][4];
    #pragma unroll
    for (int i = 0; i < 4; ++i)
        #pragma unroll
        for (int j = 0; j < 4; ++j)
            #pragma unroll
            for (int k = 0; k < 4; ++k) acc[i][j][k] = 0.f;

    const int r_ld = tid >> 3;
    const int c16 = (tid & 7) * 16;
    auto cp_chunk = [&](int c, int s) {
        const uint32_t as = sb + s * STG2;
        const uint32_t bs = as + A2_ST;
        const long akb = (long)c * 128;
        const long bko = (long)(c & 3) * NPIX * 128;
        #pragma unroll
        for (int i = 0; i < 8; ++i) {
            const int r = r_ld + i * 32;
            cp16(as + r * LDS_B + c16, Ab + (long)r * (KP * 2) + akb + c16);
        }
        #pragma unroll
        for (int i = 0; i < 2; ++i) {
            const int r = r_ld + i * 32;
            cp16(bs + r * LDS_B + c16, Bb + bko + (long)r * 128 + c16);
        }
        cp_commit();
    };

    const int a_row = lane & 15;
    const int a_koff = (lane >> 4) * 16;
    const int b_row = lane & 7;
    const int b_n8 = (lane >> 4) * 8;
    const int b_koff = ((lane >> 3) & 1) * 16;

    cp_chunk(0, 0);

    for (int c = 0; c < NCHUNK; ++c) {
        const int s = c & 1;
        if (c + 1 < NCHUNK) cp_chunk(c + 1, s ^ 1);
        if (c + 1 < NCHUNK) cp_wait<1>(); else cp_wait<0>();
        __syncthreads();

        const uint32_t as = sb + s * STG2;
        const uint32_t bs = as + A2_ST;
        #pragma unroll
        for (int ks = 0; ks < 4; ++ks) {
            uint32_t afr[4][4], bfr[4][2];
            #pragma unroll
            for (int mt = 0; mt < 4; ++mt)
                ldsm_x4(afr[mt], as + (wm + mt * 16 + a_row) * LDS_B + ks * 32 + a_koff);
            #pragma unroll
            for (int np = 0; np < 2; ++np) {
                uint32_t bq[4];
                ldsm_x4(bq, bs + (wn + np * 16 + b_n8 + b_row) * LDS_B + ks * 32 + b_koff);
                bfr[np * 2][0] = bq[0]; bfr[np * 2][1] = bq[1];
                bfr[np * 2 + 1][0] = bq[2]; bfr[np * 2 + 1][1] = bq[3];
            }
            #pragma unroll
            for (int mt = 0; mt < 4; ++mt)
                #pragma unroll
                for (int nt = 0; nt < 4; ++nt)
                    mma16816(acc[mt][nt], afr[mt], bfr[nt]);
        }
        __syncthreads();
    }

    // ---- epilogue: bias + LayerNorm over the 256 rows ----------------------
    const int er = lane >> 2;
    const int ec = (lane & 3) * 2;

    float bo[8], ga[8];
    #pragma unroll
    for (int mt = 0; mt < 4; ++mt) {
        const int r0 = wm + mt * 16 + er;
        bo[mt * 2] = bout[r0];        bo[mt * 2 + 1] = bout[r0 + 8];
        ga[mt * 2] = gam[r0];         ga[mt * 2 + 1] = gam[r0 + 8];
    }

    float cs[4][2], cq[4][2];
    #pragma unroll
    for (int nt = 0; nt < 4; ++nt)
        #pragma unroll
        for (int par = 0; par < 2; ++par) {
            float s = 0.f, q = 0.f;
            #pragma unroll
            for (int mt = 0; mt < 4; ++mt) {
                float v0 = acc[mt][nt][par]     + bo[mt * 2];
                float v1 = acc[mt][nt][par + 2] + bo[mt * 2 + 1];
                acc[mt][nt][par] = v0;
                acc[mt][nt][par + 2] = v1;
                s += v0 + v1;
                q += v0 * v0 + v1 * v1;
            }
            cs[nt][par] = s;
            cq[nt][par] = q;
        }
    #pragma unroll
    for (int off = 4; off < 32; off <<= 1)
        #pragma unroll
        for (int nt = 0; nt < 4; ++nt)
            #pragma unroll
            for (int par = 0; par < 2; ++par) {
                cs[nt][par] += __shfl_xor_sync(0xFFFFFFFFu, cs[nt][par], off);
                cq[nt][par] += __shfl_xor_sync(0xFFFFFFFFu, cq[nt][par], off);
            }

    float* red = (float*)smem;
    float2* lnp = (float2*)(smem + 2048);
    __syncthreads();
    if (er == 0) {
        const int wr = wid >> 1;
        #pragma unroll
        for (int nt = 0; nt < 4; ++nt)
            #pragma unroll
            for (int par = 0; par < 2; ++par) {
                const int col = wn + nt * 8 + ec + par;
                red[(wr * 64 + col) * 2]     = cs[nt][par];
                red[(wr * 64 + col) * 2 + 1] = cq[nt][par];
            }
    }
    __syncthreads();
    if (tid < 64) {
        float s = 0.f, q = 0.f;
        #pragma unroll
        for (int wr = 0; wr < 4; ++wr) {
            s += red[(wr * 64 + tid) * 2];
            q += red[(wr * 64 + tid) * 2 + 1];
        }
        const float mean = s * (1.f / 256.f);
        const float var = q * (1.f / 256.f) - mean * mean;
        lnp[tid] = make_float2(mean, rsqrtf(var + 1e-5f));
    }
    __syncthreads();

    #pragma unroll
    for (int mt = 0; mt < 4; ++mt)
        #pragma unroll
        for (int nt = 0; nt < 4; ++nt) {
            const float2 l0 = lnp[wn + nt * 8 + ec];
            const float2 l1 = lnp[wn + nt * 8 + ec + 1];
            float* p0 = Cb + (long)(wm + mt * 16 + er) * 4096 + wn + nt * 8 + ec;
            *reinterpret_cast<float2*>(p0) = make_float2(
                (acc[mt][nt][0] - l0.x) * l0.y * ga[mt * 2],
                (acc[mt][nt][1] - l1.x) * l1.y * ga[mt * 2]);
            *reinterpret_cast<float2*>(p0 + 8L * 4096) = make_float2(
                (acc[mt][nt][2] - l0.x) * l0.y * ga[mt * 2 + 1],
                (acc[mt][nt][3] - l1.x) * l1.y * ga[mt * 2 + 1]);
        }
}

// ---------------------------------------------------------------------------
// W split (fp16 hi/lo)
// ---------------------------------------------------------------------------
__global__ __launch_bounds__(256) void conv_w_kernel(const float* __restrict__ w)
{
    const int m = blockIdx.x, c = threadIdx.x;
    const float v = w[m * 256 + c];
    const __half h = __float2half(v);
    g_W2[(long)m * KP + c] = h;
    g_W2[(long)m * KP + 256 + c] = __float2half(v - __half2float(h));
}

// ---------------------------------------------------------------------------
// x transpose (hi only) into chunk-major g_Bx[b][c/64][p][64]
// ---------------------------------------------------------------------------
__global__ __launch_bounds__(256) void transpose_x(const float* __restrict__ x, int zoff)
{
    __shared__ float sm[32][129];
    const int b = blockIdx.z + zoff, c0 = blockIdx.y * 32, p0 = blockIdx.x * 128;
    const float* xb = x + ((long)b * 256 + c0) * 4096 + p0;
    const int tid = threadIdx.x;

    #pragma unroll
    for (int i = 0; i < 16; ++i) {
        const int u = tid + i * 256;
        sm[u >> 7][u & 127] = xb[(long)(u >> 7) * 4096 + (u & 127)];
    }
    __syncthreads();

    const int rr = tid >> 1, j0 = (tid & 1) * 16;
    __align__(16) __half hv[16];
    #pragma unroll
    for (int j = 0; j < 16; ++j) hv[j] = __float2half(sm[j0 + j][rr]);

    __half* ob = g_Bx + (((long)b * 4 + (c0 >> 6)) * NPIX + p0 + rr) * 64 + (c0 & 63) + j0;
    reinterpret_cast<uint4*>(ob)[0] = reinterpret_cast<const uint4*>(hv)[0];
    reinterpret_cast<uint4*>(ob)[1] = reinterpret_cast<const uint4*>(hv)[1];
}

// ---------------------------------------------------------------------------
// context partials with fused k-softmax normalization (combines k partials)
// ---------------------------------------------------------------------------
__global__ __launch_bounds__(256) void context_kernel()
{
    const int bh = blockIdx.x;
    const int ch = blockIdx.y;
    const int b = bh >> 3, h = bh & 7;
    const float* kbase = g_qkv + (long)b * QKV_ROWS * NPIX + (long)(256 + h * DH) * 4096 + ch * 1024;
    const float* vbase = g_qkv + (long)b * QKV_ROWS * NPIX + (long)(512 + h * DH) * 4096 + ch * 1024;

    __shared__ float ks[DH][129];
    __shared__ float vs[DH][129];
    __shared__ float km[DH], ki[DH];

    const int tid = threadIdx.x;
    if (tid < DH) {
        const float2* pp = g_kpart + ((long)b * 256 + h * DH + tid) * 32;
        float m = -1e30f;
        #pragma unroll
        for (int i = 0; i < 32; ++i) m = fmaxf(m, pp[i].x);
        float s = 0.f;
        #pragma unroll
        for (int i = 0; i < 32; ++i) s += pp[i].y * expf(pp[i].x - m);
        km[tid] = m;
        ki[tid] = 1.f / s;
    }
    __syncthreads();

    const int d = tid >> 3;
    const int e0 = (tid & 7) * 4;
    float acc[4] = {0.f, 0.f, 0.f, 0.f};

    for (int pc = 0; pc < 1024; pc += 128) {
        __syncthreads();
        #pragma unroll
        for (int i = 0; i < 4; ++i) {
            const int f4 = tid + i * 256;
            const int r = f4 >> 5, c4 = (f4 & 31) << 2;
            const float4 kv = *reinterpret_cast<const float4*>(kbase + (long)r * 4096 + pc + c4);
            const float4 vv = *reinterpret_cast<const float4*>(vbase + (long)r * 4096 + pc + c4);
            const float mm = km[r], ii = ki[r];
            ks[r][c4]   = expf(kv.x - mm) * ii;
            ks[r][c4+1] = expf(kv.y - mm) * ii;
            ks[r][c4+2] = expf(kv.z - mm) * ii;
            ks[r][c4+3] = expf(kv.w - mm) * ii;
            vs[r][c4] = vv.x; vs[r][c4+1] = vv.y; vs[r][c4+2] = vv.z; vs[r][c4+3] = vv.w;
        }
        __syncthreads();
        #pragma unroll 4
        for (int pp = 0; pp < 128; ++pp) {
            const float kd = ks[d][pp];
            acc[0] += kd * vs[e0 + 0][pp];
            acc[1] += kd * vs[e0 + 1][pp];
            acc[2] += kd * vs[e0 + 2][pp];
            acc[3] += kd * vs[e0 + 3][pp];
        }
    }
    const float invn = 1.f / (float)NPIX;
    float* op = g_ctxp + ((long)bh * 4 + ch) * (DH * DH) + d * DH + e0;
    #pragma unroll
    for (int j = 0; j < 4; ++j) op[j] = acc[j] * invn;
}

// ---------------------------------------------------------------------------
// buildM -> fp16 [Mh|Ml] in g_A2
// ---------------------------------------------------------------------------
__global__ __launch_bounds__(256) void buildM_kernel(const float* __restrict__ wout)
{
    const int bh = blockIdx.x;
    const int b = bh >> 3, h = bh & 7;

    __shared__ float cs[DH][DH + 1];
    const int tid = threadIdx.x;

    for (int i = tid; i < DH * DH; i += 256) {
        float s = 0.f;
        #pragma unroll
        for (int ch = 0; ch < 4; ++ch)
            s += g_ctxp[((long)bh * 4 + ch) * (DH * DH) + i];
        cs[i >> 5][i & 31] = s;
    }
    __syncthreads();

    float w[DH];
    const float* wr = wout + (long)tid * 256 + h * DH;
    #pragma unroll
    for (int e = 0; e < DH; ++e) w[e] = wr[e];

    __align__(16) __half hi[DH], lo[DH];
    for (int d = 0; d < DH; ++d) {
        float s = 0.f;
        #pragma unroll
        for (int e = 0; e < DH; ++e) s += w[e] * cs[d][e];
        const __half hh = __float2half(s);
        hi[d] = hh;
        lo[d] = __float2half(s - __half2float(hh));
    }
    __half* ob = g_A2 + ((long)b * HID + tid) * KP + h * DH;
    #pragma unroll
    for (int i = 0; i < 4; ++i) {
        reinterpret_cast<uint4*>(ob)[i] = reinterpret_cast<const uint4*>(hi)[i];
        reinterpret_cast<uint4*>(ob + 256)[i] = reinterpret_cast<const uint4*>(lo)[i];
    }
}

// ---------------------------------------------------------------------------
extern "C" void kernel_launch(void* const* d_in, const int* in_sizes, int n_in,
                              void* d_out, int out_size)
{
    (void)in_sizes; (void)n_in; (void)out_size;
    const float* x     = (const float*)d_in[0];
    const float* w_qkv = (const float*)d_in[1];
    const float* w_out = (const float*)d_in[2];
    const float* b_out = (const float*)d_in[3];
    const float* g     = (const float*)d_in[4];
    float* out = (float*)d_out;

    __half *p_W = nullptr, *p_Bx = nullptr, *p_Bq = nullptr, *p_A2 = nullptr;
    cudaGetSymbolAddress((void**)&p_W,   g_W2);
    cudaGetSymbolAddress((void**)&p_Bx,  g_Bx);
    cudaGetSymbolAddress((void**)&p_Bq,  g_Bq);
    cudaGetSymbolAddress((void**)&p_A2,  g_A2);

    cudaFuncSetAttribute(gemm_mma, cudaFuncAttributeMaxDynamicSharedMemorySize, SMEM1);
    cudaFuncSetAttribute(gemm_ln,  cudaFuncAttributeMaxDynamicSharedMemorySize, 2 * STG2);

    // prep
    conv_w_kernel<<<QKV_ROWS, 256>>>(w_qkv);
    transpose_x<<<dim3(32, 8, 8), 256>>>(x, 0);
    transpose_x<<<dim3(32, 8, 8), 256>>>(x, 8);

    // QKV GEMM + fused q-softmax / k-partials
    gemm_mma<<<dim3(6, 32, BATCH), 256, SMEM1>>>(p_W, p_Bx);

    // context partials (combines k partials, fused normalization)
    context_kernel<<<dim3(BATCH * HEADS, 4), 256>>>();

    // M fold -> fp16 split
    buildM_kernel<<<BATCH * HEADS, 256>>>(w_out);

    // y GEMM + bias + LayerNorm -> d_out
    gemm_ln<<<dim3(64, 1, BATCH), 256, 2 * STG2>>>(p_A2, p_Bq, b_out, g, out);
}

// round 6
// speedup vs baseline: 2.7899x; 1.0341x over previous
#include <cuda_runtime.h>
#include <cuda_fp16.h>
#include <stdint.h>

#define BATCH   16
#define HID     256
#define HEADS   8
#define DH      32
#define NPIX    4096
#define QKV_ROWS 768
#define KP      512          // fp16 2-term split K' = 2*256
#define NCHUNK  8            // K' / 64

// ---------------- device scratch ------------------------------------------
__device__ __half g_ek[BATCH * 256 * NPIX];             // exp(k-4) fp16, 32 MB
__device__ __half g_v [BATCH * 256 * NPIX];             // v raw fp16, 32 MB
__device__ __half g_W2[QKV_ROWS * KP];                  // [Wh|Wl] [768,512]
__device__ __half g_Bx[BATCH * 4 * NPIX * 64];          // chunk-major x^T (hi), 32 MB
__device__ __half g_Bq[BATCH * 4 * NPIX * 64];          // chunk-major softmaxed q^T, 32 MB
__device__ __half g_A2[BATCH * HID * KP];               // [Mh|Ml] [b,256,512]
__device__ float g_ctxp[BATCH * HEADS * 4 * DH * DH];   // context partials
__device__ float g_kpart[BATCH * 256 * 32];             // k row sumexp partials per 128-col block

// ---------------- PTX helpers (base ISA only) ------------------------------
__device__ __forceinline__ uint32_t smem_u32(const void* p) {
    uint32_t a;
    asm("{ .reg .u64 t; cvta.to.shared.u64 t, %1; cvt.u32.u64 %0, t; }" : "=r"(a) : "l"(p));
    return a;
}
__device__ __forceinline__ void cp16(uint32_t saddr, const void* gaddr) {
    asm volatile("cp.async.cg.shared.global [%0], [%1], 16;" :: "r"(saddr), "l"(gaddr) : "memory");
}
__device__ __forceinline__ void cp_commit() {
    asm volatile("cp.async.commit_group;" ::: "memory");
}
template <int N>
__device__ __forceinline__ void cp_wait() {
    asm volatile("cp.async.wait_group %0;" :: "n"(N) : "memory");
}
__device__ __forceinline__ void ldsm_x4(uint32_t* r, uint32_t addr) {
    asm volatile("ldmatrix.sync.aligned.m8n8.x4.shared.b16 {%0,%1,%2,%3}, [%4];"
                 : "=r"(r[0]), "=r"(r[1]), "=r"(r[2]), "=r"(r[3]) : "r"(addr));
}
__device__ __forceinline__ void mma16816(float* c, const uint32_t* a, const uint32_t* b) {
    asm volatile(
        "mma.sync.aligned.m16n8k16.row.col.f32.f16.f16.f32 "
        "{%0,%1,%2,%3}, {%4,%5,%6,%7}, {%8,%9}, {%0,%1,%2,%3};"
        : "+f"(c[0]), "+f"(c[1]), "+f"(c[2]), "+f"(c[3])
        : "r"(a[0]), "r"(a[1]), "r"(a[2]), "r"(a[3]), "r"(b[0]), "r"(b[1]));
}

#define LDS_B 144
#define OP1 (128 * LDS_B)
#define STG1 (2 * OP1)           // 36864 per stage
#define SMEM1 (3 * STG1)         // 110592, 3 stages

// ---------------------------------------------------------------------------
// GEMM1 + fused epilogues. 128 threads, 4 warps of 64x64, CTA 128x128, BK=64.
// bx 0-1: q (softmax -> g_Bq fp16); 2-3: k (exp(k-4) fp16 + row sums);
// 4-5: v (raw fp16).
// ---------------------------------------------------------------------------
__global__ __launch_bounds__(128, 2) void gemm_mma(
    const __half* __restrict__ A, const __half* __restrict__ B)
{
    extern __shared__ char smem[];
    const uint32_t sb = smem_u32(smem);
    const int tid = threadIdx.x;
    const int wid = tid >> 5;
    const int lane = tid & 31;
    const int bx = blockIdx.x, by = blockIdx.y, b = blockIdx.z;

    const char* Ab = (const char*)(A + (long)bx * 128 * KP);
    const char* Bb = (const char*)B + ((long)b * 4 * NPIX + (long)by * 128) * 128;

    const int wm = (wid >> 1) * 64;
    const int wn = (wid & 1) * 64;

    float acc[4][8][4];
    #pragma unroll
    for (int i = 0; i < 4; ++i)
        #pragma unroll
        for (int j = 0; j < 8; ++j)
            #pragma unroll
            for (int k = 0; k < 4; ++k) acc[i][j][k] = 0.f;

    const int r_ld = tid >> 3;              // 0..15
    const int c16 = (tid & 7) * 16;
    auto cp_chunk = [&](int c) {
        const uint32_t as = sb + (c % 3) * STG1;
        const uint32_t bs = as + OP1;
        const long akb = (long)c * 128;
        const long bko = (long)(c & 3) * NPIX * 128;
        #pragma unroll
        for (int i = 0; i < 8; ++i) {
            const int r = r_ld + i * 16;
            const uint32_t so = r * LDS_B + c16;
            cp16(as + so, Ab + (long)r * (KP * 2) + akb + c16);
            cp16(bs + so, Bb + bko + (long)r * 128 + c16);
        }
        cp_commit();
    };

    const int a_row = lane & 15;
    const int a_koff = (lane >> 4) * 16;
    const int b_row = lane & 7;
    const int b_n8 = (lane >> 4) * 8;
    const int b_koff = ((lane >> 3) & 1) * 16;

    cp_chunk(0);
    cp_chunk(1);

    for (int c = 0; c < NCHUNK; ++c) {
        if (c < NCHUNK - 1) cp_wait<1>(); else cp_wait<0>();
        __syncthreads();
        if (c + 2 < NCHUNK) cp_chunk(c + 2);

        const uint32_t as = sb + (c % 3) * STG1;
        const uint32_t bs = as + OP1;
        #pragma unroll
        for (int ks = 0; ks < 4; ++ks) {
            uint32_t afr[4][4], bfr[8][2];
            #pragma unroll
            for (int mt = 0; mt < 4; ++mt)
                ldsm_x4(afr[mt], as + (wm + mt * 16 + a_row) * LDS_B + ks * 32 + a_koff);
            #pragma unroll
            for (int np = 0; np < 4; ++np) {
                uint32_t bq[4];
                ldsm_x4(bq, bs + (wn + np * 16 + b_n8 + b_row) * LDS_B + ks * 32 + b_koff);
                bfr[np * 2][0] = bq[0]; bfr[np * 2][1] = bq[1];
                bfr[np * 2 + 1][0] = bq[2]; bfr[np * 2 + 1][1] = bq[3];
            }
            #pragma unroll
            for (int mt = 0; mt < 4; ++mt)
                #pragma unroll
                for (int nt = 0; nt < 8; ++nt)
                    mma16816(acc[mt][nt], afr[mt], bfr[nt]);
        }
    }

    const int er = lane >> 2;
    const int ec = (lane & 3) * 2;

    if (bx >= 4) {
        // ---- v: raw fp16 ----------------------------------------------------
        __half* Vb = g_v + ((long)b * 256 + (long)(bx - 4) * 128) * 4096 + by * 128;
        #pragma unroll
        for (int mt = 0; mt < 4; ++mt)
            #pragma unroll
            for (int nt = 0; nt < 8; ++nt) {
                const long r0 = wm + mt * 16 + er;
                const int c0 = wn + nt * 8 + ec;
                *reinterpret_cast<__half2*>(Vb + r0 * 4096 + c0) =
                    __floats2half2_rn(acc[mt][nt][0], acc[mt][nt][1]);
                *reinterpret_cast<__half2*>(Vb + (r0 + 8) * 4096 + c0) =
                    __floats2half2_rn(acc[mt][nt][2], acc[mt][nt][3]);
            }
        return;
    }

    if (bx >= 2) {
        // ---- k: exp(k-4) fp16 + row-sum partials ---------------------------
        __half* Ek = g_ek + ((long)b * 256 + (long)(bx - 2) * 128) * 4096 + by * 128;
        float rs[8];
        #pragma unroll
        for (int i = 0; i < 8; ++i) rs[i] = 0.f;
        #pragma unroll
        for (int mt = 0; mt < 4; ++mt)
            #pragma unroll
            for (int nt = 0; nt < 8; ++nt) {
                const float e0 = expf(acc[mt][nt][0] - 4.f);
                const float e1 = expf(acc[mt][nt][1] - 4.f);
                const float e2 = expf(acc[mt][nt][2] - 4.f);
                const float e3 = expf(acc[mt][nt][3] - 4.f);
                const long r0 = wm + mt * 16 + er;
                const int c0 = wn + nt * 8 + ec;
                *reinterpret_cast<__half2*>(Ek + r0 * 4096 + c0) = __floats2half2_rn(e0, e1);
                *reinterpret_cast<__half2*>(Ek + (r0 + 8) * 4096 + c0) = __floats2half2_rn(e2, e3);
                rs[mt * 2] += e0 + e1;
                rs[mt * 2 + 1] += e2 + e3;
            }
        #pragma unroll
        for (int off = 1; off < 4; off <<= 1)
            #pragma unroll
            for (int i = 0; i < 8; ++i)
                rs[i] += __shfl_xor_sync(0xFFFFFFFFu, rs[i], off);

        float* ssum = (float*)smem;   // [128 rows][2 col-halves]
        __syncthreads();
        if ((lane & 3) == 0) {
            #pragma unroll
            for (int mt = 0; mt < 4; ++mt)
                #pragma unroll
                for (int h2 = 0; h2 < 2; ++h2)
                    ssum[(wm + mt * 16 + er + h2 * 8) * 2 + (wid & 1)] = rs[mt * 2 + h2];
        }
        __syncthreads();
        if (tid < 128)
            g_kpart[((long)b * 256 + (bx - 2) * 128 + tid) * 32 + by] =
                ssum[tid * 2] + ssum[tid * 2 + 1];
        return;
    }

    // ---- q: stage to smem, softmax over d, emit fp16 chunk-major -----------
    float* sfl = (float*)smem;
    __syncthreads();
    #pragma unroll
    for (int mt = 0; mt < 4; ++mt)
        #pragma unroll
        for (int nt = 0; nt < 8; ++nt) {
            const int r0 = wm + mt * 16 + er;
            const int c0 = wn + nt * 8 + ec;
            sfl[r0 * 129 + c0] = acc[mt][nt][0];
            sfl[r0 * 129 + c0 + 1] = acc[mt][nt][1];
            sfl[(r0 + 8) * 129 + c0] = acc[mt][nt][2];
            sfl[(r0 + 8) * 129 + c0 + 1] = acc[mt][nt][3];
        }
    __syncthreads();

    #pragma unroll
    for (int t = tid; t < 512; t += 128) {
        const int hb = t >> 7;
        const int col = t & 127;
        float v[DH];
        float m = -1e30f;
        #pragma unroll
        for (int d = 0; d < DH; ++d) {
            v[d] = sfl[(hb * 32 + d) * 129 + col];
            m = fmaxf(m, v[d]);
        }
        float s = 0.f;
        #pragma unroll
        for (int d = 0; d < DH; ++d) { v[d] = expf(v[d] - m); s += v[d]; }
        const float inv = 0.1767766952966369f / s;
        __align__(16) __half o[DH];
        #pragma unroll
        for (int d = 0; d < DH; ++d) o[d] = __float2half(v[d] * inv);

        const int gh = bx * 4 + hb;
        const long gcol = (long)by * 128 + col;
        __half* ob = g_Bq + (((long)b * 4 + (gh >> 1)) * NPIX + gcol) * 64 + (gh & 1) * 32;
        #pragma unroll
        for (int i = 0; i < 4; ++i)
            reinterpret_cast<uint4*>(ob)[i] = reinterpret_cast<const uint4*>(o)[i];
    }
}

// ---------------------------------------------------------------------------
// GEMM2 + fused bias + LayerNorm. CTA tile 256x64. 2-stage cp.async.
// ---------------------------------------------------------------------------
#define A2_ST (256 * LDS_B)
#define B2_ST (64 * LDS_B)
#define STG2  (A2_ST + B2_ST)

__global__ __launch_bounds__(256, 1) void gemm_ln(
    const __half* __restrict__ A, const __half* __restrict__ B,
    const float* __restrict__ bout, const float* __restrict__ gam,
    float* __restrict__ out)
{
    extern __shared__ char smem[];
    const uint32_t sb = smem_u32(smem);
    const int tid = threadIdx.x;
    const int wid = tid >> 5;
    const int lane = tid & 31;
    const int b = blockIdx.z;
    const int n0 = blockIdx.x * 64;

    const char* Ab = (const char*)(A + (long)b * HID * KP);
    const char* Bb = (const char*)B + ((long)b * 4 * NPIX + n0) * 128;
    float* Cb = out + (long)b * HID * NPIX + n0;

    const int wm = (wid >> 1) * 64;
    const int wn = (wid & 1) * 32;

    float acc[4][4][4];
    #pragma unroll
    for (int i = 0; i < 4; ++i)
        #pragma unroll
        for (int j = 0; j < 4; ++j)
            #pragma unroll
            for (int k = 0; k < 4; ++k) acc[i][j][k] = 0.f;

    const int r_ld = tid >> 3;
    const int c16 = (tid & 7) * 16;
    auto cp_chunk = [&](int c, int s) {
        const uint32_t as = sb + s * STG2;
        const uint32_t bs = as + A2_ST;
        const long akb = (long)c * 128;
        const long bko = (long)(c & 3) * NPIX * 128;
        #pragma unroll
        for (int i = 0; i < 8; ++i) {
            const int r = r_ld + i * 32;
            cp16(as + r * LDS_B + c16, Ab + (long)r * (KP * 2) + akb + c16);
        }
        #pragma unroll
        for (int i = 0; i < 2; ++i) {
            const int r = r_ld + i * 32;
            cp16(bs + r * LDS_B + c16, Bb + bko + (long)r * 128 + c16);
        }
        cp_commit();
    };

    const int a_row = lane & 15;
    const int a_koff = (lane >> 4) * 16;
    const int b_row = lane & 7;
    const int b_n8 = (lane >> 4) * 8;
    const int b_koff = ((lane >> 3) & 1) * 16;

    cp_chunk(0, 0);

    for (int c = 0; c < NCHUNK; ++c) {
        const int s = c & 1;
        if (c + 1 < NCHUNK) cp_chunk(c + 1, s ^ 1);
        if (c + 1 < NCHUNK) cp_wait<1>(); else cp_wait<0>();
        __syncthreads();

        const uint32_t as = sb + s * STG2;
        const uint32_t bs = as + A2_ST;
        #pragma unroll
        for (int ks = 0; ks < 4; ++ks) {
            uint32_t afr[4][4], bfr[4][2];
            #pragma unroll
            for (int mt = 0; mt < 4; ++mt)
                ldsm_x4(afr[mt], as + (wm + mt * 16 + a_row) * LDS_B + ks * 32 + a_koff);
            #pragma unroll
            for (int np = 0; np < 2; ++np) {
                uint32_t bq[4];
                ldsm_x4(bq, bs + (wn + np * 16 + b_n8 + b_row) * LDS_B + ks * 32 + b_koff);
                bfr[np * 2][0] = bq[0]; bfr[np * 2][1] = bq[1];
                bfr[np * 2 + 1][0] = bq[2]; bfr[np * 2 + 1][1] = bq[3];
            }
            #pragma unroll
            for (int mt = 0; mt < 4; ++mt)
                #pragma unroll
                for (int nt = 0; nt < 4; ++nt)
                    mma16816(acc[mt][nt], afr[mt], bfr[nt]);
        }
        __syncthreads();
    }

    const int er = lane >> 2;
    const int ec = (lane & 3) * 2;

    float bo[8], ga[8];
    #pragma unroll
    for (int mt = 0; mt < 4; ++mt) {
        const int r0 = wm + mt * 16 + er;
        bo[mt * 2] = bout[r0];        bo[mt * 2 + 1] = bout[r0 + 8];
        ga[mt * 2] = gam[r0];         ga[mt * 2 + 1] = gam[r0 + 8];
    }

    float cs[4][2], cq[4][2];
    #pragma unroll
    for (int nt = 0; nt < 4; ++nt)
        #pragma unroll
        for (int par = 0; par < 2; ++par) {
            float s = 0.f, q = 0.f;
            #pragma unroll
            for (int mt = 0; mt < 4; ++mt) {
                float v0 = acc[mt][nt][par]     + bo[mt * 2];
                float v1 = acc[mt][nt][par + 2] + bo[mt * 2 + 1];
                acc[mt][nt][par] = v0;
                acc[mt][nt][par + 2] = v1;
                s += v0 + v1;
                q += v0 * v0 + v1 * v1;
            }
            cs[nt][par] = s;
            cq[nt][par] = q;
        }
    #pragma unroll
    for (int off = 4; off < 32; off <<= 1)
        #pragma unroll
        for (int nt = 0; nt < 4; ++nt)
            #pragma unroll
            for (int par = 0; par < 2; ++par) {
                cs[nt][par] += __shfl_xor_sync(0xFFFFFFFFu, cs[nt][par], off);
                cq[nt][par] += __shfl_xor_sync(0xFFFFFFFFu, cq[nt][par], off);
            }

    float* red = (float*)smem;
    float2* lnp = (float2*)(smem + 2048);
    __syncthreads();
    if (er == 0) {
        const int wr = wid >> 1;
        #pragma unroll
        for (int nt = 0; nt < 4; ++nt)
            #pragma unroll
            for (int par = 0; par < 2; ++par) {
                const int col = wn + nt * 8 + ec + par;
                red[(wr * 64 + col) * 2]     = cs[nt][par];
                red[(wr * 64 + col) * 2 + 1] = cq[nt][par];
            }
    }
    __syncthreads();
    if (tid < 64) {
        float s = 0.f, q = 0.f;
        #pragma unroll
        for (int wr = 0; wr < 4; ++wr) {
            s += red[(wr * 64 + tid) * 2];
            q += red[(wr * 64 + tid) * 2 + 1];
        }
        const float mean = s * (1.f / 256.f);
        const float var = q * (1.f / 256.f) - mean * mean;
        lnp[tid] = make_float2(mean, rsqrtf(var + 1e-5f));
    }
    __syncthreads();

    #pragma unroll
    for (int mt = 0; mt < 4; ++mt)
        #pragma unroll
        for (int nt = 0; nt < 4; ++nt) {
            const float2 l0 = lnp[wn + nt * 8 + ec];
            const float2 l1 = lnp[wn + nt * 8 + ec + 1];
            float* p0 = Cb + (long)(wm + mt * 16 + er) * 4096 + wn + nt * 8 + ec;
            *reinterpret_cast<float2*>(p0) = make_float2(
                (acc[mt][nt][0] - l0.x) * l0.y * ga[mt * 2],
                (acc[mt][nt][1] - l1.x) * l1.y * ga[mt * 2]);
            *reinterpret_cast<float2*>(p0 + 8L * 4096) = make_float2(
                (acc[mt][nt][2] - l0.x) * l0.y * ga[mt * 2 + 1],
                (acc[mt][nt][3] - l1.x) * l1.y * ga[mt * 2 + 1]);
        }
}

// ---------------------------------------------------------------------------
__global__ __launch_bounds__(256) void conv_w_kernel(const float* __restrict__ w)
{
    const int m = blockIdx.x, c = threadIdx.x;
    const float v = w[m * 256 + c];
    const __half h = __float2half(v);
    g_W2[(long)m * KP + c] = h;
    g_W2[(long)m * KP + 256 + c] = __float2half(v - __half2float(h));
}

// ---------------------------------------------------------------------------
__global__ __launch_bounds__(256) void transpose_x(const float* __restrict__ x, int zoff)
{
    __shared__ float sm[32][129];
    const int b = blockIdx.z + zoff, c0 = blockIdx.y * 32, p0 = blockIdx.x * 128;
    const float* xb = x + ((long)b * 256 + c0) * 4096 + p0;
    const int tid = threadIdx.x;

    #pragma unroll
    for (int i = 0; i < 16; ++i) {
        const int u = tid + i * 256;
        sm[u >> 7][u & 127] = xb[(long)(u >> 7) * 4096 + (u & 127)];
    }
    __syncthreads();

    const int rr = tid >> 1, j0 = (tid & 1) * 16;
    __align__(16) __half hv[16];
    #pragma unroll
    for (int j = 0; j < 16; ++j) hv[j] = __float2half(sm[j0 + j][rr]);

    __half* ob = g_Bx + (((long)b * 4 + (c0 >> 6)) * NPIX + p0 + rr) * 64 + (c0 & 63) + j0;
    reinterpret_cast<uint4*>(ob)[0] = reinterpret_cast<const uint4*>(hv)[0];
    reinterpret_cast<uint4*>(ob)[1] = reinterpret_cast<const uint4*>(hv)[1];
}

// ---------------------------------------------------------------------------
// context partials from fp16 expk / v. grid (128, 4). No expf here.
// ---------------------------------------------------------------------------
__global__ __launch_bounds__(256) void context_kernel()
{
    const int bh = blockIdx.x;
    const int ch = blockIdx.y;
    const int b = bh >> 3, h = bh & 7;
    const __half* kb = g_ek + ((long)b * 256 + h * DH) * 4096 + ch * 1024;
    const __half* vb = g_v  + ((long)b * 256 + h * DH) * 4096 + ch * 1024;

    __shared__ float ks[DH][129];
    __shared__ float vs[DH][129];
    __shared__ float ki[DH];

    const int tid = threadIdx.x;
    if (tid < DH) {
        const float* pp = g_kpart + ((long)b * 256 + h * DH + tid) * 32;
        float s = 0.f;
        #pragma unroll
        for (int i = 0; i < 32; ++i) s += pp[i];
        ki[tid] = 1.f / s;
    }
    __syncthreads();

    const int d = tid >> 3;
    const int e0 = (tid & 7) * 4;
    float acc[4] = {0.f, 0.f, 0.f, 0.f};

    for (int pc = 0; pc < 1024; pc += 128) {
        __syncthreads();
        #pragma unroll
        for (int i = 0; i < 2; ++i) {
            const int u = tid + i * 256;          // 0..511
            const int r = u >> 4, c8 = (u & 15) * 8;
            const uint4 kv = *reinterpret_cast<const uint4*>(kb + (long)r * 4096 + pc + c8);
            const uint4 vv = *reinterpret_cast<const uint4*>(vb + (long)r * 4096 + pc + c8);
            const float ii = ki[r];
            const __half2* kh = reinterpret_cast<const __half2*>(&kv);
            const __half2* vh = reinterpret_cast<const __half2*>(&vv);
            #pragma unroll
            for (int j = 0; j < 4; ++j) {
                const float2 kf = __half22float2(kh[j]);
                const float2 vf = __half22float2(vh[j]);
                ks[r][c8 + j * 2]     = kf.x * ii;
                ks[r][c8 + j * 2 + 1] = kf.y * ii;
                vs[r][c8 + j * 2]     = vf.x;
                vs[r][c8 + j * 2 + 1] = vf.y;
            }
        }
        __syncthreads();
        #pragma unroll 4
        for (int pp = 0; pp < 128; ++pp) {
            const float kd = ks[d][pp];
            acc[0] += kd * vs[e0 + 0][pp];
            acc[1] += kd * vs[e0 + 1][pp];
            acc[2] += kd * vs[e0 + 2][pp];
            acc[3] += kd * vs[e0 + 3][pp];
        }
    }
    const float invn = 1.f / (float)NPIX;
    float* op = g_ctxp + ((long)bh * 4 + ch) * (DH * DH) + d * DH + e0;
    #pragma unroll
    for (int j = 0; j < 4; ++j) op[j] = acc[j] * invn;
}

// ---------------------------------------------------------------------------
__global__ __launch_bounds__(256) void buildM_kernel(const float* __restrict__ wout)
{
    const int bh = blockIdx.x;
    const int b = bh >> 3, h = bh & 7;

    __shared__ float cs[DH][DH + 1];
    const int tid = threadIdx.x;

    for (int i = tid; i < DH * DH; i += 256) {
        float s = 0.f;
        #pragma unroll
        for (int ch = 0; ch < 4; ++ch)
            s += g_ctxp[((long)bh * 4 + ch) * (DH * DH) + i];
        cs[i >> 5][i & 31] = s;
    }
    __syncthreads();

    float w[DH];
    const float* wr = wout + (long)tid * 256 + h * DH;
    #pragma unroll
    for (int e = 0; e < DH; ++e) w[e] = wr[e];

    __align__(16) __half hi[DH], lo[DH];
    for (int d = 0; d < DH; ++d) {
        float s = 0.f;
        #pragma unroll
        for (int e = 0; e < DH; ++e) s += w[e] * cs[d][e];
        const __half hh = __float2half(s);
        hi[d] = hh;
        lo[d] = __float2half(s - __half2float(hh));
    }
    __half* ob = g_A2 + ((long)b * HID + tid) * KP + h * DH;
    #pragma unroll
    for (int i = 0; i < 4; ++i) {
        reinterpret_cast<uint4*>(ob)[i] = reinterpret_cast<const uint4*>(hi)[i];
        reinterpret_cast<uint4*>(ob + 256)[i] = reinterpret_cast<const uint4*>(lo)[i];
    }
}

// ---------------------------------------------------------------------------
extern "C" void kernel_launch(void* const* d_in, const int* in_sizes, int n_in,
                              void* d_out, int out_size)
{
    (void)in_sizes; (void)n_in; (void)out_size;
    const float* x     = (const float*)d_in[0];
    const float* w_qkv = (const float*)d_in[1];
    const float* w_out = (const float*)d_in[2];
    const float* b_out = (const float*)d_in[3];
    const float* g     = (const float*)d_in[4];
    float* out = (float*)d_out;

    __half *p_W = nullptr, *p_Bx = nullptr, *p_Bq = nullptr, *p_A2 = nullptr;
    cudaGetSymbolAddress((void**)&p_W,   g_W2);
    cudaGetSymbolAddress((void**)&p_Bx,  g_Bx);
    cudaGetSymbolAddress((void**)&p_Bq,  g_Bq);
    cudaGetSymbolAddress((void**)&p_A2,  g_A2);

    cudaFuncSetAttribute(gemm_mma, cudaFuncAttributeMaxDynamicSharedMemorySize, SMEM1);
    cudaFuncSetAttribute(gemm_ln,  cudaFuncAttributeMaxDynamicSharedMemorySize, 2 * STG2);

    conv_w_kernel<<<QKV_ROWS, 256>>>(w_qkv);
    transpose_x<<<dim3(32, 8, 8), 256>>>(x, 0);
    transpose_x<<<dim3(32, 8, 8), 256>>>(x, 8);

    // QKV GEMM + fused q-softmax / expk / v epilogues
    gemm_mma<<<dim3(6, 32, BATCH), 128, SMEM1>>>(p_W, p_Bx);

    // context partials (fp16 inputs, no expf)
    context_kernel<<<dim3(BATCH * HEADS, 4), 256>>>();

    // M fold -> fp16 split
    buildM_kernel<<<BATCH * HEADS, 256>>>(w_out);

    // y GEMM + bias + LayerNorm -> d_out
    gemm_ln<<<dim3(64, 1, BATCH), 256, 2 * STG2>>>(p_A2, p_Bq, b_out, g, out);
}

// round 7
// speedup vs baseline: 3.6276x; 1.3003x over previous
#include <cuda_runtime.h>
#include <cuda_fp16.h>
#include <stdint.h>

#define BATCH   16
#define HID     256
#define HEADS   8
#define DH      32
#define NPIX    4096
#define QKV_ROWS 768
#define KP      256          // single-term fp16, K' = 256
#define NCHUNK  4            // K' / 64

// ---------------- device scratch ------------------------------------------
__device__ __half g_ek[BATCH * 256 * NPIX];             // exp(k-4) fp16, 32 MB
__device__ __half g_v [BATCH * 256 * NPIX];             // v raw fp16, 32 MB
__device__ __half g_W2[QKV_ROWS * KP];                  // W fp16 [768,256]
__device__ __half g_Bx[BATCH * 4 * NPIX * 64];          // chunk-major x^T, 32 MB
__device__ __half g_Bq[BATCH * 4 * NPIX * 64];          // chunk-major softmaxed q^T, 32 MB
__device__ __half g_A2[BATCH * HID * KP];               // M fp16 [b,256,256]
__device__ float g_ctxp[BATCH * HEADS * 4 * DH * DH];   // context partials
__device__ float g_kpart[BATCH * 256 * 32];             // k row sumexp partials per 128-col block

// ---------------- PTX helpers (base ISA only) ------------------------------
__device__ __forceinline__ uint32_t smem_u32(const void* p) {
    uint32_t a;
    asm("{ .reg .u64 t; cvta.to.shared.u64 t, %1; cvt.u32.u64 %0, t; }" : "=r"(a) : "l"(p));
    return a;
}
__device__ __forceinline__ void cp16(uint32_t saddr, const void* gaddr) {
    asm volatile("cp.async.cg.shared.global [%0], [%1], 16;" :: "r"(saddr), "l"(gaddr) : "memory");
}
__device__ __forceinline__ void cp_commit() {
    asm volatile("cp.async.commit_group;" ::: "memory");
}
template <int N>
__device__ __forceinline__ void cp_wait() {
    asm volatile("cp.async.wait_group %0;" :: "n"(N) : "memory");
}
__device__ __forceinline__ void ldsm_x4(uint32_t* r, uint32_t addr) {
    asm volatile("ldmatrix.sync.aligned.m8n8.x4.shared.b16 {%0,%1,%2,%3}, [%4];"
                 : "=r"(r[0]), "=r"(r[1]), "=r"(r[2]), "=r"(r[3]) : "r"(addr));
}
__device__ __forceinline__ void mma16816(float* c, const uint32_t* a, const uint32_t* b) {
    asm volatile(
        "mma.sync.aligned.m16n8k16.row.col.f32.f16.f16.f32 "
        "{%0,%1,%2,%3}, {%4,%5,%6,%7}, {%8,%9}, {%0,%1,%2,%3};"
        : "+f"(c[0]), "+f"(c[1]), "+f"(c[2]), "+f"(c[3])
        : "r"(a[0]), "r"(a[1]), "r"(a[2]), "r"(a[3]), "r"(b[0]), "r"(b[1]));
}

#define LDS_B 144
#define OP1 (128 * LDS_B)
#define STG1 (2 * OP1)           // 36864 per stage
#define SMEM1 (3 * STG1)         // 110592, 3 stages

// ---------------------------------------------------------------------------
// GEMM1 + fused epilogues. 128 threads, 4 warps of 64x64, CTA 128x128, BK=64.
// bx 0-1: q (softmax -> g_Bq fp16); 2-3: k (exp(k-4) fp16 + row sums);
// 4-5: v (raw fp16).
// ---------------------------------------------------------------------------
__global__ __launch_bounds__(128, 2) void gemm_mma(
    const __half* __restrict__ A, const __half* __restrict__ B)
{
    extern __shared__ char smem[];
    const uint32_t sb = smem_u32(smem);
    const int tid = threadIdx.x;
    const int wid = tid >> 5;
    const int lane = tid & 31;
    const int bx = blockIdx.x, by = blockIdx.y, b = blockIdx.z;

    const char* Ab = (const char*)(A + (long)bx * 128 * KP);
    const char* Bb = (const char*)B + ((long)b * 4 * NPIX + (long)by * 128) * 128;

    const int wm = (wid >> 1) * 64;
    const int wn = (wid & 1) * 64;

    float acc[4][8][4];
    #pragma unroll
    for (int i = 0; i < 4; ++i)
        #pragma unroll
        for (int j = 0; j < 8; ++j)
            #pragma unroll
            for (int k = 0; k < 4; ++k) acc[i][j][k] = 0.f;

    const int r_ld = tid >> 3;              // 0..15
    const int c16 = (tid & 7) * 16;
    auto cp_chunk = [&](int c) {
        const uint32_t as = sb + (c % 3) * STG1;
        const uint32_t bs = as + OP1;
        const long akb = (long)c * 128;
        const long bko = (long)c * NPIX * 128;
        #pragma unroll
        for (int i = 0; i < 8; ++i) {
            const int r = r_ld + i * 16;
            const uint32_t so = r * LDS_B + c16;
            cp16(as + so, Ab + (long)r * (KP * 2) + akb + c16);
            cp16(bs + so, Bb + bko + (long)r * 128 + c16);
        }
        cp_commit();
    };

    const int a_row = lane & 15;
    const int a_koff = (lane >> 4) * 16;
    const int b_row = lane & 7;
    const int b_n8 = (lane >> 4) * 8;
    const int b_koff = ((lane >> 3) & 1) * 16;

    cp_chunk(0);
    cp_chunk(1);

    for (int c = 0; c < NCHUNK; ++c) {
        if (c < NCHUNK - 1) cp_wait<1>(); else cp_wait<0>();
        __syncthreads();
        if (c + 2 < NCHUNK) cp_chunk(c + 2);

        const uint32_t as = sb + (c % 3) * STG1;
        const uint32_t bs = as + OP1;
        #pragma unroll
        for (int ks = 0; ks < 4; ++ks) {
            uint32_t afr[4][4], bfr[8][2];
            #pragma unroll
            for (int mt = 0; mt < 4; ++mt)
                ldsm_x4(afr[mt], as + (wm + mt * 16 + a_row) * LDS_B + ks * 32 + a_koff);
            #pragma unroll
            for (int np = 0; np < 4; ++np) {
                uint32_t bq[4];
                ldsm_x4(bq, bs + (wn + np * 16 + b_n8 + b_row) * LDS_B + ks * 32 + b_koff);
                bfr[np * 2][0] = bq[0]; bfr[np * 2][1] = bq[1];
                bfr[np * 2 + 1][0] = bq[2]; bfr[np * 2 + 1][1] = bq[3];
            }
            #pragma unroll
            for (int mt = 0; mt < 4; ++mt)
                #pragma unroll
                for (int nt = 0; nt < 8; ++nt)
                    mma16816(acc[mt][nt], afr[mt], bfr[nt]);
        }
    }

    const int er = lane >> 2;
    const int ec = (lane & 3) * 2;

    if (bx >= 4) {
        // ---- v: raw fp16 ----------------------------------------------------
        __half* Vb = g_v + ((long)b * 256 + (long)(bx - 4) * 128) * 4096 + by * 128;
        #pragma unroll
        for (int mt = 0; mt < 4; ++mt)
            #pragma unroll
            for (int nt = 0; nt < 8; ++nt) {
                const long r0 = wm + mt * 16 + er;
                const int c0 = wn + nt * 8 + ec;
                *reinterpret_cast<__half2*>(Vb + r0 * 4096 + c0) =
                    __floats2half2_rn(acc[mt][nt][0], acc[mt][nt][1]);
                *reinterpret_cast<__half2*>(Vb + (r0 + 8) * 4096 + c0) =
                    __floats2half2_rn(acc[mt][nt][2], acc[mt][nt][3]);
            }
        return;
    }

    if (bx >= 2) {
        // ---- k: exp(k-4) fp16 + row-sum partials ---------------------------
        __half* Ek = g_ek + ((long)b * 256 + (long)(bx - 2) * 128) * 4096 + by * 128;
        float rs[8];
        #pragma unroll
        for (int i = 0; i < 8; ++i) rs[i] = 0.f;
        #pragma unroll
        for (int mt = 0; mt < 4; ++mt)
            #pragma unroll
            for (int nt = 0; nt < 8; ++nt) {
                const float e0 = expf(acc[mt][nt][0] - 4.f);
                const float e1 = expf(acc[mt][nt][1] - 4.f);
                const float e2 = expf(acc[mt][nt][2] - 4.f);
                const float e3 = expf(acc[mt][nt][3] - 4.f);
                const long r0 = wm + mt * 16 + er;
                const int c0 = wn + nt * 8 + ec;
                *reinterpret_cast<__half2*>(Ek + r0 * 4096 + c0) = __floats2half2_rn(e0, e1);
                *reinterpret_cast<__half2*>(Ek + (r0 + 8) * 4096 + c0) = __floats2half2_rn(e2, e3);
                rs[mt * 2] += e0 + e1;
                rs[mt * 2 + 1] += e2 + e3;
            }
        #pragma unroll
        for (int off = 1; off < 4; off <<= 1)
            #pragma unroll
            for (int i = 0; i < 8; ++i)
                rs[i] += __shfl_xor_sync(0xFFFFFFFFu, rs[i], off);

        float* ssum = (float*)smem;
        __syncthreads();
        if ((lane & 3) == 0) {
            #pragma unroll
            for (int mt = 0; mt < 4; ++mt)
                #pragma unroll
                for (int h2 = 0; h2 < 2; ++h2)
                    ssum[(wm + mt * 16 + er + h2 * 8) * 2 + (wid & 1)] = rs[mt * 2 + h2];
        }
        __syncthreads();
        if (tid < 128)
            g_kpart[((long)b * 256 + (bx - 2) * 128 + tid) * 32 + by] =
                ssum[tid * 2] + ssum[tid * 2 + 1];
        return;
    }

    // ---- q: stage to smem, softmax over d, emit fp16 chunk-major -----------
    float* sfl = (float*)smem;
    __syncthreads();
    #pragma unroll
    for (int mt = 0; mt < 4; ++mt)
        #pragma unroll
        for (int nt = 0; nt < 8; ++nt) {
            const int r0 = wm + mt * 16 + er;
            const int c0 = wn + nt * 8 + ec;
            sfl[r0 * 129 + c0] = acc[mt][nt][0];
            sfl[r0 * 129 + c0 + 1] = acc[mt][nt][1];
            sfl[(r0 + 8) * 129 + c0] = acc[mt][nt][2];
            sfl[(r0 + 8) * 129 + c0 + 1] = acc[mt][nt][3];
        }
    __syncthreads();

    #pragma unroll
    for (int t = tid; t < 512; t += 128) {
        const int hb = t >> 7;
        const int col = t & 127;
        float v[DH];
        float m = -1e30f;
        #pragma unroll
        for (int d = 0; d < DH; ++d) {
            v[d] = sfl[(hb * 32 + d) * 129 + col];
            m = fmaxf(m, v[d]);
        }
        float s = 0.f;
        #pragma unroll
        for (int d = 0; d < DH; ++d) { v[d] = expf(v[d] - m); s += v[d]; }
        const float inv = 0.1767766952966369f / s;
        __align__(16) __half o[DH];
        #pragma unroll
        for (int d = 0; d < DH; ++d) o[d] = __float2half(v[d] * inv);

        const int gh = bx * 4 + hb;
        const long gcol = (long)by * 128 + col;
        __half* ob = g_Bq + (((long)b * 4 + (gh >> 1)) * NPIX + gcol) * 64 + (gh & 1) * 32;
        #pragma unroll
        for (int i = 0; i < 4; ++i)
            reinterpret_cast<uint4*>(ob)[i] = reinterpret_cast<const uint4*>(o)[i];
    }
}

// ---------------------------------------------------------------------------
// GEMM2 + fused bias + LayerNorm. CTA tile 256x64. 2-stage cp.async.
// ---------------------------------------------------------------------------
#define A2_ST (256 * LDS_B)
#define B2_ST (64 * LDS_B)
#define STG2  (A2_ST + B2_ST)

__global__ __launch_bounds__(256, 1) void gemm_ln(
    const __half* __restrict__ A, const __half* __restrict__ B,
    const float* __restrict__ bout, const float* __restrict__ gam,
    float* __restrict__ out)
{
    extern __shared__ char smem[];
    const uint32_t sb = smem_u32(smem);
    const int tid = threadIdx.x;
    const int wid = tid >> 5;
    const int lane = tid & 31;
    const int b = blockIdx.z;
    const int n0 = blockIdx.x * 64;

    const char* Ab = (const char*)(A + (long)b * HID * KP);
    const char* Bb = (const char*)B + ((long)b * 4 * NPIX + n0) * 128;
    float* Cb = out + (long)b * HID * NPIX + n0;

    const int wm = (wid >> 1) * 64;
    const int wn = (wid & 1) * 32;

    float acc[4][4][4];
    #pragma unroll
    for (int i = 0; i < 4; ++i)
        #pragma unroll
        for (int j = 0; j < 4; ++j)
            #pragma unroll
            for (int k = 0; k < 4; ++k) acc[i][j][k] = 0.f;

    const int r_ld = tid >> 3;
    const int c16 = (tid & 7) * 16;
    auto cp_chunk = [&](int c, int s) {
        const uint32_t as = sb + s * STG2;
        const uint32_t bs = as + A2_ST;
        const long akb = (long)c * 128;
        const long bko = (long)c * NPIX * 128;
        #pragma unroll
        for (int i = 0; i < 8; ++i) {
            const int r = r_ld + i * 32;
            cp16(as + r * LDS_B + c16, Ab + (long)r * (KP * 2) + akb + c16);
        }
        #pragma unroll
        for (int i = 0; i < 2; ++i) {
            const int r = r_ld + i * 32;
            cp16(bs + r * LDS_B + c16, Bb + bko + (long)r * 128 + c16);
        }
        cp_commit();
    };

    const int a_row = lane & 15;
    const int a_koff = (lane >> 4) * 16;
    const int b_row = lane & 7;
    const int b_n8 = (lane >> 4) * 8;
    const int b_koff = ((lane >> 3) & 1) * 16;

    cp_chunk(0, 0);

    for (int c = 0; c < NCHUNK; ++c) {
        const int s = c & 1;
        if (c + 1 < NCHUNK) cp_chunk(c + 1, s ^ 1);
        if (c + 1 < NCHUNK) cp_wait<1>(); else cp_wait<0>();
        __syncthreads();

        const uint32_t as = sb + s * STG2;
        const uint32_t bs = as + A2_ST;
        #pragma unroll
        for (int ks = 0; ks < 4; ++ks) {
            uint32_t afr[4][4], bfr[4][2];
            #pragma unroll
            for (int mt = 0; mt < 4; ++mt)
                ldsm_x4(afr[mt], as + (wm + mt * 16 + a_row) * LDS_B + ks * 32 + a_koff);
            #pragma unroll
            for (int np = 0; np < 2; ++np) {
                uint32_t bq[4];
                ldsm_x4(bq, bs + (wn + np * 16 + b_n8 + b_row) * LDS_B + ks * 32 + b_koff);
                bfr[np * 2][0] = bq[0]; bfr[np * 2][1] = bq[1];
                bfr[np * 2 + 1][0] = bq[2]; bfr[np * 2 + 1][1] = bq[3];
            }
            #pragma unroll
            for (int mt = 0; mt < 4; ++mt)
                #pragma unroll
                for (int nt = 0; nt < 4; ++nt)
                    mma16816(acc[mt][nt], afr[mt], bfr[nt]);
        }
        __syncthreads();
    }

    const int er = lane >> 2;
    const int ec = (lane & 3) * 2;

    float bo[8], ga[8];
    #pragma unroll
    for (int mt = 0; mt < 4; ++mt) {
        const int r0 = wm + mt * 16 + er;
        bo[mt * 2] = bout[r0];        bo[mt * 2 + 1] = bout[r0 + 8];
        ga[mt * 2] = gam[r0];         ga[mt * 2 + 1] = gam[r0 + 8];
    }

    float cs[4][2], cq[4][2];
    #pragma unroll
    for (int nt = 0; nt < 4; ++nt)
        #pragma unroll
        for (int par = 0; par < 2; ++par) {
            float s = 0.f, q = 0.f;
            #pragma unroll
            for (int mt = 0; mt < 4; ++mt) {
                float v0 = acc[mt][nt][par]     + bo[mt * 2];
                float v1 = acc[mt][nt][par + 2] + bo[mt * 2 + 1];
                acc[mt][nt][par] = v0;
                acc[mt][nt][par + 2] = v1;
                s += v0 + v1;
                q += v0 * v0 + v1 * v1;
            }
            cs[nt][par] = s;
            cq[nt][par] = q;
        }
    #pragma unroll
    for (int off = 4; off < 32; off <<= 1)
        #pragma unroll
        for (int nt = 0; nt < 4; ++nt)
            #pragma unroll
            for (int par = 0; par < 2; ++par) {
                cs[nt][par] += __shfl_xor_sync(0xFFFFFFFFu, cs[nt][par], off);
                cq[nt][par] += __shfl_xor_sync(0xFFFFFFFFu, cq[nt][par], off);
            }

    float* red = (float*)smem;
    float2* lnp = (float2*)(smem + 2048);
    __syncthreads();
    if (er == 0) {
        const int wr = wid >> 1;
        #pragma unroll
        for (int nt = 0; nt < 4; ++nt)
            #pragma unroll
            for (int par = 0; par < 2; ++par) {
                const int col = wn + nt * 8 + ec + par;
                red[(wr * 64 + col) * 2]     = cs[nt][par];
                red[(wr * 64 + col) * 2 + 1] = cq[nt][par];
            }
    }
    __syncthreads();
    if (tid < 64) {
        float s = 0.f, q = 0.f;
        #pragma unroll
        for (int wr = 0; wr < 4; ++wr) {
            s += red[(wr * 64 + tid) * 2];
            q += red[(wr * 64 + tid) * 2 + 1];
        }
        const float mean = s * (1.f / 256.f);
        const float var = q * (1.f / 256.f) - mean * mean;
        lnp[tid] = make_float2(mean, rsqrtf(var + 1e-5f));
    }
    __syncthreads();

    #pragma unroll
    for (int mt = 0; mt < 4; ++mt)
        #pragma unroll
        for (int nt = 0; nt < 4; ++nt) {
            const float2 l0 = lnp[wn + nt * 8 + ec];
            const float2 l1 = lnp[wn + nt * 8 + ec + 1];
            float* p0 = Cb + (long)(wm + mt * 16 + er) * 4096 + wn + nt * 8 + ec;
            *reinterpret_cast<float2*>(p0) = make_float2(
                (acc[mt][nt][0] - l0.x) * l0.y * ga[mt * 2],
                (acc[mt][nt][1] - l1.x) * l1.y * ga[mt * 2]);
            *reinterpret_cast<float2*>(p0 + 8L * 4096) = make_float2(
                (acc[mt][nt][2] - l0.x) * l0.y * ga[mt * 2 + 1],
                (acc[mt][nt][3] - l1.x) * l1.y * ga[mt * 2 + 1]);
        }
}

// ---------------------------------------------------------------------------
__global__ __launch_bounds__(256) void conv_w_kernel(const float* __restrict__ w)
{
    const int m = blockIdx.x, c = threadIdx.x;
    g_W2[(long)m * KP + c] = __float2half(w[m * 256 + c]);
}

// ---------------------------------------------------------------------------
__global__ __launch_bounds__(256) void transpose_x(const float* __restrict__ x, int zoff)
{
    __shared__ float sm[32][129];
    const int b = blockIdx.z + zoff, c0 = blockIdx.y * 32, p0 = blockIdx.x * 128;
    const float* xb = x + ((long)b * 256 + c0) * 4096 + p0;
    const int tid = threadIdx.x;

    #pragma unroll
    for (int i = 0; i < 16; ++i) {
        const int u = tid + i * 256;
        sm[u >> 7][u & 127] = xb[(long)(u >> 7) * 4096 + (u & 127)];
    }
    __syncthreads();

    const int rr = tid >> 1, j0 = (tid & 1) * 16;
    __align__(16) __half hv[16];
    #pragma unroll
    for (int j = 0; j < 16; ++j) hv[j] = __float2half(sm[j0 + j][rr]);

    __half* ob = g_Bx + (((long)b * 4 + (c0 >> 6)) * NPIX + p0 + rr) * 64 + (c0 & 63) + j0;
    reinterpret_cast<uint4*>(ob)[0] = reinterpret_cast<const uint4*>(hv)[0];
    reinterpret_cast<uint4*>(ob)[1] = reinterpret_cast<const uint4*>(hv)[1];
}

// ---------------------------------------------------------------------------
// context partials from fp16 expk / v. grid (128, 4). No expf here.
// ---------------------------------------------------------------------------
__global__ __launch_bounds__(256) void context_kernel()
{
    const int bh = blockIdx.x;
    const int ch = blockIdx.y;
    const int b = bh >> 3, h = bh & 7;
    const __half* kb = g_ek + ((long)b * 256 + h * DH) * 4096 + ch * 1024;
    const __half* vb = g_v  + ((long)b * 256 + h * DH) * 4096 + ch * 1024;

    __shared__ float ks[DH][129];
    __shared__ float vs[DH][129];
    __shared__ float ki[DH];

    const int tid = threadIdx.x;
    if (tid < DH) {
        const float* pp = g_kpart + ((long)b * 256 + h * DH + tid) * 32;
        float s = 0.f;
        #pragma unroll
        for (int i = 0; i < 32; ++i) s += pp[i];
        ki[tid] = 1.f / s;
    }
    __syncthreads();

    const int d = tid >> 3;
    const int e0 = (tid & 7) * 4;
    float acc[4] = {0.f, 0.f, 0.f, 0.f};

    for (int pc = 0; pc < 1024; pc += 128) {
        __syncthreads();
        #pragma unroll
        for (int i = 0; i < 2; ++i) {
            const int u = tid + i * 256;
            const int r = u >> 4, c8 = (u & 15) * 8;
            const uint4 kv = *reinterpret_cast<const uint4*>(kb + (long)r * 4096 + pc + c8);
            const uint4 vv = *reinterpret_cast<const uint4*>(vb + (long)r * 4096 + pc + c8);
            const float ii = ki[r];
            const __half2* kh = reinterpret_cast<const __half2*>(&kv);
            const __half2* vh = reinterpret_cast<const __half2*>(&vv);
            #pragma unroll
            for (int j = 0; j < 4; ++j) {
                const float2 kf = __half22float2(kh[j]);
                const float2 vf = __half22float2(vh[j]);
                ks[r][c8 + j * 2]     = kf.x * ii;
                ks[r][c8 + j * 2 + 1] = kf.y * ii;
                vs[r][c8 + j * 2]     = vf.x;
                vs[r][c8 + j * 2 + 1] = vf.y;
            }
        }
        __syncthreads();
        #pragma unroll 4
        for (int pp = 0; pp < 128; ++pp) {
            const float kd = ks[d][pp];
            acc[0] += kd * vs[e0 + 0][pp];
            acc[1] += kd * vs[e0 + 1][pp];
            acc[2] += kd * vs[e0 + 2][pp];
            acc[3] += kd * vs[e0 + 3][pp];
        }
    }
    const float invn = 1.f / (float)NPIX;
    float* op = g_ctxp + ((long)bh * 4 + ch) * (DH * DH) + d * DH + e0;
    #pragma unroll
    for (int j = 0; j < 4; ++j) op[j] = acc[j] * invn;
}

// ---------------------------------------------------------------------------
// buildM -> single fp16 M in g_A2
// ---------------------------------------------------------------------------
__global__ __launch_bounds__(256) void buildM_kernel(const float* __restrict__ wout)
{
    const int bh = blockIdx.x;
    const int b = bh >> 3, h = bh & 7;

    __shared__ float cs[DH][DH + 1];
    const int tid = threadIdx.x;

    for (int i = tid; i < DH * DH; i += 256) {
        float s = 0.f;
        #pragma unroll
        for (int ch = 0; ch < 4; ++ch)
            s += g_ctxp[((long)bh * 4 + ch) * (DH * DH) + i];
        cs[i >> 5][i & 31] = s;
    }
    __syncthreads();

    float w[DH];
    const float* wr = wout + (long)tid * 256 + h * DH;
    #pragma unroll
    for (int e = 0; e < DH; ++e) w[e] = wr[e];

    __align__(16) __half hi[DH];
    for (int d = 0; d < DH; ++d) {
        float s = 0.f;
        #pragma unroll
        for (int e = 0; e < DH; ++e) s += w[e] * cs[d][e];
        hi[d] = __float2half(s);
    }
    __half* ob = g_A2 + ((long)b * HID + tid) * KP + h * DH;
    #pragma unroll
    for (int i = 0; i < 4; ++i)
        reinterpret_cast<uint4*>(ob)[i] = reinterpret_cast<const uint4*>(hi)[i];
}

// ---------------------------------------------------------------------------
extern "C" void kernel_launch(void* const* d_in, const int* in_sizes, int n_in,
                              void* d_out, int out_size)
{
    (void)in_sizes; (void)n_in; (void)out_size;
    const float* x     = (const float*)d_in[0];
    const float* w_qkv = (const float*)d_in[1];
    const float* w_out = (const float*)d_in[2];
    const float* b_out = (const float*)d_in[3];
    const float* g     = (const float*)d_in[4];
    float* out = (float*)d_out;

    __half *p_W = nullptr, *p_Bx = nullptr, *p_Bq = nullptr, *p_A2 = nullptr;
    cudaGetSymbolAddress((void**)&p_W,   g_W2);
    cudaGetSymbolAddress((void**)&p_Bx,  g_Bx);
    cudaGetSymbolAddress((void**)&p_Bq,  g_Bq);
    cudaGetSymbolAddress((void**)&p_A2,  g_A2);

    cudaFuncSetAttribute(gemm_mma, cudaFuncAttributeMaxDynamicSharedMemorySize, SMEM1);
    cudaFuncSetAttribute(gemm_ln,  cudaFuncAttributeMaxDynamicSharedMemorySize, 2 * STG2);

    conv_w_kernel<<<QKV_ROWS, 256>>>(w_qkv);
    transpose_x<<<dim3(32, 8, 8), 256>>>(x, 0);
    transpose_x<<<dim3(32, 8, 8), 256>>>(x, 8);

    // QKV GEMM (single fp16, K=256) + fused q-softmax / expk / v epilogues
    gemm_mma<<<dim3(6, 32, BATCH), 128, SMEM1>>>(p_W, p_Bx);

    // context partials (fp16 inputs, no expf)
    context_kernel<<<dim3(BATCH * HEADS, 4), 256>>>();

    // M fold -> single fp16
    buildM_kernel<<<BATCH * HEADS, 256>>>(w_out);

    // y GEMM (K=256) + bias + LayerNorm -> d_out
    gemm_ln<<<dim3(64, 1, BATCH), 256, 2 * STG2>>>(p_A2, p_Bq, b_out, g, out);
}

// round 8
// speedup vs baseline: 4.4892x; 1.2375x over previous
#include <cuda_runtime.h>
#include <cuda_fp16.h>
#include <stdint.h>

#define BATCH   16
#define HID     256
#define HEADS   8
#define DH      32
#define NPIX    4096
#define QKV_ROWS 768
#define KP      256          // single-term fp16, K' = 256
#define NCHUNK  4            // K' / 64

// ---------------- device scratch ------------------------------------------
__device__ __half g_ek[BATCH * 256 * NPIX];             // exp(k-4) fp16, 32 MB
__device__ __half g_v [BATCH * 256 * NPIX];             // v raw fp16, 32 MB
__device__ __half g_W2[QKV_ROWS * KP];                  // W fp16 [768,256]
__device__ __half g_Bx[BATCH * 4 * NPIX * 64];          // chunk-major x^T, 32 MB
__device__ __half g_Bq[BATCH * 4 * NPIX * 64];          // chunk-major softmaxed q^T, 32 MB
__device__ __half g_A2[BATCH * HID * KP];               // M fp16 [b,256,256]
__device__ float g_ctxp[BATCH * HEADS * 4 * DH * DH];   // context partials
__device__ float g_kpart[BATCH * 256 * 32];             // k row sumexp partials per 128-col block

// ---------------- PTX helpers (base ISA only) ------------------------------
__device__ __forceinline__ uint32_t smem_u32(const void* p) {
    uint32_t a;
    asm("{ .reg .u64 t; cvta.to.shared.u64 t, %1; cvt.u32.u64 %0, t; }" : "=r"(a) : "l"(p));
    return a;
}
__device__ __forceinline__ void cp16(uint32_t saddr, const void* gaddr) {
    asm volatile("cp.async.cg.shared.global [%0], [%1], 16;" :: "r"(saddr), "l"(gaddr) : "memory");
}
__device__ __forceinline__ void cp_commit() {
    asm volatile("cp.async.commit_group;" ::: "memory");
}
template <int N>
__device__ __forceinline__ void cp_wait() {
    asm volatile("cp.async.wait_group %0;" :: "n"(N) : "memory");
}
__device__ __forceinline__ void ldsm_x4(uint32_t* r, uint32_t addr) {
    asm volatile("ldmatrix.sync.aligned.m8n8.x4.shared.b16 {%0,%1,%2,%3}, [%4];"
                 : "=r"(r[0]), "=r"(r[1]), "=r"(r[2]), "=r"(r[3]) : "r"(addr));
}
__device__ __forceinline__ void mma16816(float* c, const uint32_t* a, const uint32_t* b) {
    asm volatile(
        "mma.sync.aligned.m16n8k16.row.col.f32.f16.f16.f32 "
        "{%0,%1,%2,%3}, {%4,%5,%6,%7}, {%8,%9}, {%0,%1,%2,%3};"
        : "+f"(c[0]), "+f"(c[1]), "+f"(c[2]), "+f"(c[3])
        : "r"(a[0]), "r"(a[1]), "r"(a[2]), "r"(a[3]), "r"(b[0]), "r"(b[1]));
}

#define LDS_B 144
#define OP1 (128 * LDS_B)
#define STG1 (2 * OP1)           // 36864 per stage
#define SMEM1 (3 * STG1)         // 110592, 3 stages

// ---------------------------------------------------------------------------
// GEMM1 + fused epilogues. 256 threads, 8 warps of 64x32, CTA 128x128, BK=64.
// bx 0-1: q (softmax -> g_Bq fp16); 2-3: k (exp(k-4) fp16 + row sums);
// 4-5: v (raw fp16).
// ---------------------------------------------------------------------------
__global__ __launch_bounds__(256, 2) void gemm_mma(
    const __half* __restrict__ A, const __half* __restrict__ B)
{
    extern __shared__ char smem[];
    const uint32_t sb = smem_u32(smem);
    const int tid = threadIdx.x;
    const int wid = tid >> 5;
    const int lane = tid & 31;
    const int bx = blockIdx.x, by = blockIdx.y, b = blockIdx.z;

    const char* Ab = (const char*)(A + (long)bx * 128 * KP);
    const char* Bb = (const char*)B + ((long)b * 4 * NPIX + (long)by * 128) * 128;

    const int wm = (wid >> 2) * 64;
    const int wn = (wid & 3) * 32;

    float acc[4][4][4];
    #pragma unroll
    for (int i = 0; i < 4; ++i)
        #pragma unroll
        for (int j = 0; j < 4; ++j)
            #pragma unroll
            for (int k = 0; k < 4; ++k) acc[i][j][k] = 0.f;

    const int r_ld = tid >> 3;              // 0..31
    const int c16 = (tid & 7) * 16;
    auto cp_chunk = [&](int c) {
        const uint32_t as = sb + (c % 3) * STG1;
        const uint32_t bs = as + OP1;
        const long akb = (long)c * 128;
        const long bko = (long)c * NPIX * 128;
        #pragma unroll
        for (int i = 0; i < 4; ++i) {
            const int r = r_ld + i * 32;
            const uint32_t so = r * LDS_B + c16;
            cp16(as + so, Ab + (long)r * (KP * 2) + akb + c16);
            cp16(bs + so, Bb + bko + (long)r * 128 + c16);
        }
        cp_commit();
    };

    const int a_row = lane & 15;
    const int a_koff = (lane >> 4) * 16;
    const int b_row = lane & 7;
    const int b_n8 = (lane >> 4) * 8;
    const int b_koff = ((lane >> 3) & 1) * 16;

    cp_chunk(0);
    cp_chunk(1);

    for (int c = 0; c < NCHUNK; ++c) {
        if (c < NCHUNK - 1) cp_wait<1>(); else cp_wait<0>();
        __syncthreads();
        if (c + 2 < NCHUNK) cp_chunk(c + 2);

        const uint32_t as = sb + (c % 3) * STG1;
        const uint32_t bs = as + OP1;
        #pragma unroll
        for (int ks = 0; ks < 4; ++ks) {
            uint32_t afr[4][4], bfr[4][2];
            #pragma unroll
            for (int mt = 0; mt < 4; ++mt)
                ldsm_x4(afr[mt], as + (wm + mt * 16 + a_row) * LDS_B + ks * 32 + a_koff);
            #pragma unroll
            for (int np = 0; np < 2; ++np) {
                uint32_t bq[4];
                ldsm_x4(bq, bs + (wn + np * 16 + b_n8 + b_row) * LDS_B + ks * 32 + b_koff);
                bfr[np * 2][0] = bq[0]; bfr[np * 2][1] = bq[1];
                bfr[np * 2 + 1][0] = bq[2]; bfr[np * 2 + 1][1] = bq[3];
            }
            #pragma unroll
            for (int mt = 0; mt < 4; ++mt)
                #pragma unroll
                for (int nt = 0; nt < 4; ++nt)
                    mma16816(acc[mt][nt], afr[mt], bfr[nt]);
        }
    }

    const int er = lane >> 2;
    const int ec = (lane & 3) * 2;

    if (bx >= 4) {
        // ---- v: raw fp16 ----------------------------------------------------
        __half* Vb = g_v + ((long)b * 256 + (long)(bx - 4) * 128) * 4096 + by * 128;
        #pragma unroll
        for (int mt = 0; mt < 4; ++mt)
            #pragma unroll
            for (int nt = 0; nt < 4; ++nt) {
                const long r0 = wm + mt * 16 + er;
                const int c0 = wn + nt * 8 + ec;
                *reinterpret_cast<__half2*>(Vb + r0 * 4096 + c0) =
                    __floats2half2_rn(acc[mt][nt][0], acc[mt][nt][1]);
                *reinterpret_cast<__half2*>(Vb + (r0 + 8) * 4096 + c0) =
                    __floats2half2_rn(acc[mt][nt][2], acc[mt][nt][3]);
            }
        return;
    }

    if (bx >= 2) {
        // ---- k: exp(k-4) fp16 + row-sum partials ---------------------------
        __half* Ek = g_ek + ((long)b * 256 + (long)(bx - 2) * 128) * 4096 + by * 128;
        float rs[8];
        #pragma unroll
        for (int i = 0; i < 8; ++i) rs[i] = 0.f;
        #pragma unroll
        for (int mt = 0; mt < 4; ++mt)
            #pragma unroll
            for (int nt = 0; nt < 4; ++nt) {
                const float e0 = __expf(acc[mt][nt][0] - 4.f);
                const float e1 = __expf(acc[mt][nt][1] - 4.f);
                const float e2 = __expf(acc[mt][nt][2] - 4.f);
                const float e3 = __expf(acc[mt][nt][3] - 4.f);
                const long r0 = wm + mt * 16 + er;
                const int c0 = wn + nt * 8 + ec;
                *reinterpret_cast<__half2*>(Ek + r0 * 4096 + c0) = __floats2half2_rn(e0, e1);
                *reinterpret_cast<__half2*>(Ek + (r0 + 8) * 4096 + c0) = __floats2half2_rn(e2, e3);
                rs[mt * 2] += e0 + e1;
                rs[mt * 2 + 1] += e2 + e3;
            }
        // sum over the 4 lanes in the quad (covers all 32 warp cols)
        #pragma unroll
        for (int off = 1; off < 4; off <<= 1)
            #pragma unroll
            for (int i = 0; i < 8; ++i)
                rs[i] += __shfl_xor_sync(0xFFFFFFFFu, rs[i], off);

        float* ssum = (float*)smem;   // [128 rows][4 col-quarters]
        __syncthreads();
        if ((lane & 3) == 0) {
            const int wq = wid & 3;
            #pragma unroll
            for (int mt = 0; mt < 4; ++mt)
                #pragma unroll
                for (int h2 = 0; h2 < 2; ++h2)
                    ssum[(wm + mt * 16 + er + h2 * 8) * 4 + wq] = rs[mt * 2 + h2];
        }
        __syncthreads();
        if (tid < 128)
            g_kpart[((long)b * 256 + (bx - 2) * 128 + tid) * 32 + by] =
                ssum[tid * 4] + ssum[tid * 4 + 1] + ssum[tid * 4 + 2] + ssum[tid * 4 + 3];
        return;
    }

    // ---- q: stage to smem, softmax over d, emit fp16 chunk-major -----------
    float* sfl = (float*)smem;
    __syncthreads();
    #pragma unroll
    for (int mt = 0; mt < 4; ++mt)
        #pragma unroll
        for (int nt = 0; nt < 4; ++nt) {
            const int r0 = wm + mt * 16 + er;
            const int c0 = wn + nt * 8 + ec;
            sfl[r0 * 129 + c0] = acc[mt][nt][0];
            sfl[r0 * 129 + c0 + 1] = acc[mt][nt][1];
            sfl[(r0 + 8) * 129 + c0] = acc[mt][nt][2];
            sfl[(r0 + 8) * 129 + c0 + 1] = acc[mt][nt][3];
        }
    __syncthreads();

    #pragma unroll
    for (int t = tid; t < 512; t += 256) {
        const int hb = t >> 7;
        const int col = t & 127;
        float v[DH];
        float m = -1e30f;
        #pragma unroll
        for (int d = 0; d < DH; ++d) {
            v[d] = sfl[(hb * 32 + d) * 129 + col];
            m = fmaxf(m, v[d]);
        }
        float s = 0.f;
        #pragma unroll
        for (int d = 0; d < DH; ++d) { v[d] = __expf(v[d] - m); s += v[d]; }
        const float inv = 0.1767766952966369f / s;
        __align__(16) __half o[DH];
        #pragma unroll
        for (int d = 0; d < DH; ++d) o[d] = __float2half(v[d] * inv);

        const int gh = bx * 4 + hb;
        const long gcol = (long)by * 128 + col;
        __half* ob = g_Bq + (((long)b * 4 + (gh >> 1)) * NPIX + gcol) * 64 + (gh & 1) * 32;
        #pragma unroll
        for (int i = 0; i < 4; ++i)
            reinterpret_cast<uint4*>(ob)[i] = reinterpret_cast<const uint4*>(o)[i];
    }
}

// ---------------------------------------------------------------------------
// GEMM2 + fused bias + LayerNorm. CTA tile 256x64. 2-stage cp.async.
// ---------------------------------------------------------------------------
#define A2_ST (256 * LDS_B)
#define B2_ST (64 * LDS_B)
#define STG2  (A2_ST + B2_ST)

__global__ __launch_bounds__(256, 2) void gemm_ln(
    const __half* __restrict__ A, const __half* __restrict__ B,
    const float* __restrict__ bout, const float* __restrict__ gam,
    float* __restrict__ out)
{
    extern __shared__ char smem[];
    const uint32_t sb = smem_u32(smem);
    const int tid = threadIdx.x;
    const int wid = tid >> 5;
    const int lane = tid & 31;
    const int b = blockIdx.z;
    const int n0 = blockIdx.x * 64;

    const char* Ab = (const char*)(A + (long)b * HID * KP);
    const char* Bb = (const char*)B + ((long)b * 4 * NPIX + n0) * 128;
    float* Cb = out + (long)b * HID * NPIX + n0;

    const int wm = (wid >> 1) * 64;
    const int wn = (wid & 1) * 32;

    float acc[4][4][4];
    #pragma unroll
    for (int i = 0; i < 4; ++i)
        #pragma unroll
        for (int j = 0; j < 4; ++j)
            #pragma unroll
            for (int k = 0; k < 4; ++k) acc[i][j][k] = 0.f;

    const int r_ld = tid >> 3;
    const int c16 = (tid & 7) * 16;
    auto cp_chunk = [&](int c, int s) {
        const uint32_t as = sb + s * STG2;
        const uint32_t bs = as + A2_ST;
        const long akb = (long)c * 128;
        const long bko = (long)c * NPIX * 128;
        #pragma unroll
        for (int i = 0; i < 8; ++i) {
            const int r = r_ld + i * 32;
            cp16(as + r * LDS_B + c16, Ab + (long)r * (KP * 2) + akb + c16);
        }
        #pragma unroll
        for (int i = 0; i < 2; ++i) {
            const int r = r_ld + i * 32;
            cp16(bs + r * LDS_B + c16, Bb + bko + (long)r * 128 + c16);
        }
        cp_commit();
    };

    const int a_row = lane & 15;
    const int a_koff = (lane >> 4) * 16;
    const int b_row = lane & 7;
    const int b_n8 = (lane >> 4) * 8;
    const int b_koff = ((lane >> 3) & 1) * 16;

    cp_chunk(0, 0);

    for (int c = 0; c < NCHUNK; ++c) {
        const int s = c & 1;
        if (c + 1 < NCHUNK) cp_chunk(c + 1, s ^ 1);
        if (c + 1 < NCHUNK) cp_wait<1>(); else cp_wait<0>();
        __syncthreads();

        const uint32_t as = sb + s * STG2;
        const uint32_t bs = as + A2_ST;
        #pragma unroll
        for (int ks = 0; ks < 4; ++ks) {
            uint32_t afr[4][4], bfr[4][2];
            #pragma unroll
            for (int mt = 0; mt < 4; ++mt)
                ldsm_x4(afr[mt], as + (wm + mt * 16 + a_row) * LDS_B + ks * 32 + a_koff);
            #pragma unroll
            for (int np = 0; np < 2; ++np) {
                uint32_t bq[4];
                ldsm_x4(bq, bs + (wn + np * 16 + b_n8 + b_row) * LDS_B + ks * 32 + b_koff);
                bfr[np * 2][0] = bq[0]; bfr[np * 2][1] = bq[1];
                bfr[np * 2 + 1][0] = bq[2]; bfr[np * 2 + 1][1] = bq[3];
            }
            #pragma unroll
            for (int mt = 0; mt < 4; ++mt)
                #pragma unroll
                for (int nt = 0; nt < 4; ++nt)
                    mma16816(acc[mt][nt], afr[mt], bfr[nt]);
        }
        __syncthreads();
    }

    const int er = lane >> 2;
    const int ec = (lane & 3) * 2;

    float bo[8], ga[8];
    #pragma unroll
    for (int mt = 0; mt < 4; ++mt) {
        const int r0 = wm + mt * 16 + er;
        bo[mt * 2] = bout[r0];        bo[mt * 2 + 1] = bout[r0 + 8];
        ga[mt * 2] = gam[r0];         ga[mt * 2 + 1] = gam[r0 + 8];
    }

    float cs[4][2], cq[4][2];
    #pragma unroll
    for (int nt = 0; nt < 4; ++nt)
        #pragma unroll
        for (int par = 0; par < 2; ++par) {
            float s = 0.f, q = 0.f;
            #pragma unroll
            for (int mt = 0; mt < 4; ++mt) {
                float v0 = acc[mt][nt][par]     + bo[mt * 2];
                float v1 = acc[mt][nt][par + 2] + bo[mt * 2 + 1];
                acc[mt][nt][par] = v0;
                acc[mt][nt][par + 2] = v1;
                s += v0 + v1;
                q += v0 * v0 + v1 * v1;
            }
            cs[nt][par] = s;
            cq[nt][par] = q;
        }
    #pragma unroll
    for (int off = 4; off < 32; off <<= 1)
        #pragma unroll
        for (int nt = 0; nt < 4; ++nt)
            #pragma unroll
            for (int par = 0; par < 2; ++par) {
                cs[nt][par] += __shfl_xor_sync(0xFFFFFFFFu, cs[nt][par], off);
                cq[nt][par] += __shfl_xor_sync(0xFFFFFFFFu, cq[nt][par], off);
            }

    float* red = (float*)smem;
    float2* lnp = (float2*)(smem + 2048);
    __syncthreads();
    if (er == 0) {
        const int wr = wid >> 1;
        #pragma unroll
        for (int nt = 0; nt < 4; ++nt)
            #pragma unroll
            for (int par = 0; par < 2; ++par) {
                const int col = wn + nt * 8 + ec + par;
                red[(wr * 64 + col) * 2]     = cs[nt][par];
                red[(wr * 64 + col) * 2 + 1] = cq[nt][par];
            }
    }
    __syncthreads();
    if (tid < 64) {
        float s = 0.f, q = 0.f;
        #pragma unroll
        for (int wr = 0; wr < 4; ++wr) {
            s += red[(wr * 64 + tid) * 2];
            q += red[(wr * 64 + tid) * 2 + 1];
        }
        const float mean = s * (1.f / 256.f);
        const float var = q * (1.f / 256.f) - mean * mean;
        lnp[tid] = make_float2(mean, rsqrtf(var + 1e-5f));
    }
    __syncthreads();

    #pragma unroll
    for (int mt = 0; mt < 4; ++mt)
        #pragma unroll
        for (int nt = 0; nt < 4; ++nt) {
            const float2 l0 = lnp[wn + nt * 8 + ec];
            const float2 l1 = lnp[wn + nt * 8 + ec + 1];
            float* p0 = Cb + (long)(wm + mt * 16 + er) * 4096 + wn + nt * 8 + ec;
            *reinterpret_cast<float2*>(p0) = make_float2(
                (acc[mt][nt][0] - l0.x) * l0.y * ga[mt * 2],
                (acc[mt][nt][1] - l1.x) * l1.y * ga[mt * 2]);
            *reinterpret_cast<float2*>(p0 + 8L * 4096) = make_float2(
                (acc[mt][nt][2] - l0.x) * l0.y * ga[mt * 2 + 1],
                (acc[mt][nt][3] - l1.x) * l1.y * ga[mt * 2 + 1]);
        }
}

// ---------------------------------------------------------------------------
__global__ __launch_bounds__(256) void conv_w_kernel(const float* __restrict__ w)
{
    const int m = blockIdx.x, c = threadIdx.x;
    g_W2[(long)m * KP + c] = __float2half(w[m * 256 + c]);
}

// ---------------------------------------------------------------------------
__global__ __launch_bounds__(256) void transpose_x(const float* __restrict__ x)
{
    __shared__ float sm[32][129];
    const int b = blockIdx.z, c0 = blockIdx.y * 32, p0 = blockIdx.x * 128;
    const float* xb = x + ((long)b * 256 + c0) * 4096 + p0;
    const int tid = threadIdx.x;

    #pragma unroll
    for (int i = 0; i < 16; ++i) {
        const int u = tid + i * 256;
        sm[u >> 7][u & 127] = xb[(long)(u >> 7) * 4096 + (u & 127)];
    }
    __syncthreads();

    const int rr = tid >> 1, j0 = (tid & 1) * 16;
    __align__(16) __half hv[16];
    #pragma unroll
    for (int j = 0; j < 16; ++j) hv[j] = __float2half(sm[j0 + j][rr]);

    __half* ob = g_Bx + (((long)b * 4 + (c0 >> 6)) * NPIX + p0 + rr) * 64 + (c0 & 63) + j0;
    reinterpret_cast<uint4*>(ob)[0] = reinterpret_cast<const uint4*>(hv)[0];
    reinterpret_cast<uint4*>(ob)[1] = reinterpret_cast<const uint4*>(hv)[1];
}

// ---------------------------------------------------------------------------
// context partials from fp16 expk / v. grid (128, 4), 128 threads.
// Register tile 2d x 4e -> 0.75 LDS per FFMA.
// ---------------------------------------------------------------------------
__global__ __launch_bounds__(128) void context_kernel()
{
    const int bh = blockIdx.x;
    const int ch = blockIdx.y;
    const int b = bh >> 3, h = bh & 7;
    const __half* kb = g_ek + ((long)b * 256 + h * DH) * 4096 + ch * 1024;
    const __half* vb = g_v  + ((long)b * 256 + h * DH) * 4096 + ch * 1024;

    __shared__ float ks[DH][129];
    __shared__ float vs[DH][129];
    __shared__ float ki[DH];

    const int tid = threadIdx.x;
    if (tid < DH) {
        const float* pp = g_kpart + ((long)b * 256 + h * DH + tid) * 32;
        float s = 0.f;
        #pragma unroll
        for (int i = 0; i < 32; ++i) s += pp[i];
        ki[tid] = 1.f / s;
    }
    __syncthreads();

    const int d0 = (tid >> 3) * 2;       // 0..30, thread owns d0, d0+1
    const int e0 = (tid & 7) * 4;
    float acc[2][4] = {};

    for (int pc = 0; pc < 1024; pc += 128) {
        __syncthreads();
        #pragma unroll
        for (int i = 0; i < 4; ++i) {
            const int u = tid + i * 128;          // 0..511
            const int r = u >> 4, c8 = (u & 15) * 8;
            const uint4 kv = *reinterpret_cast<const uint4*>(kb + (long)r * 4096 + pc + c8);
            const uint4 vv = *reinterpret_cast<const uint4*>(vb + (long)r * 4096 + pc + c8);
            const float ii = ki[r];
            const __half2* kh = reinterpret_cast<const __half2*>(&kv);
            const __half2* vh = reinterpret_cast<const __half2*>(&vv);
            #pragma unroll
            for (int j = 0; j < 4; ++j) {
                const float2 kf = __half22float2(kh[j]);
                const float2 vf = __half22float2(vh[j]);
                ks[r][c8 + j * 2]     = kf.x * ii;
                ks[r][c8 + j * 2 + 1] = kf.y * ii;
                vs[r][c8 + j * 2]     = vf.x;
                vs[r][c8 + j * 2 + 1] = vf.y;
            }
        }
        __syncthreads();
        #pragma unroll 4
        for (int pp = 0; pp < 128; ++pp) {
            const float k0 = ks[d0][pp];
            const float k1 = ks[d0 + 1][pp];
            #pragma unroll
            for (int j = 0; j < 4; ++j) {
                const float vv = vs[e0 + j][pp];
                acc[0][j] += k0 * vv;
                acc[1][j] += k1 * vv;
            }
        }
    }
    const float invn = 1.f / (float)NPIX;
    #pragma unroll
    for (int dd = 0; dd < 2; ++dd) {
        float* op = g_ctxp + ((long)bh * 4 + ch) * (DH * DH) + (d0 + dd) * DH + e0;
        #pragma unroll
        for (int j = 0; j < 4; ++j) op[j] = acc[dd][j] * invn;
    }
}

// ---------------------------------------------------------------------------
// buildM -> single fp16 M in g_A2
// ---------------------------------------------------------------------------
__global__ __launch_bounds__(256) void buildM_kernel(const float* __restrict__ wout)
{
    const int bh = blockIdx.x;
    const int b = bh >> 3, h = bh & 7;

    __shared__ float cs[DH][DH + 1];
    const int tid = threadIdx.x;

    for (int i = tid; i < DH * DH; i += 256) {
        float s = 0.f;
        #pragma unroll
        for (int ch = 0; ch < 4; ++ch)
            s += g_ctxp[((long)bh * 4 + ch) * (DH * DH) + i];
        cs[i >> 5][i & 31] = s;
    }
    __syncthreads();

    float w[DH];
    const float* wr = wout + (long)tid * 256 + h * DH;
    #pragma unroll
    for (int e = 0; e < DH; ++e) w[e] = wr[e];

    __align__(16) __half hi[DH];
    for (int d = 0; d < DH; ++d) {
        float s = 0.f;
        #pragma unroll
        for (int e = 0; e < DH; ++e) s += w[e] * cs[d][e];
        hi[d] = __float2half(s);
    }
    __half* ob = g_A2 + ((long)b * HID + tid) * KP + h * DH;
    #pragma unroll
    for (int i = 0; i < 4; ++i)
        reinterpret_cast<uint4*>(ob)[i] = reinterpret_cast<const uint4*>(hi)[i];
}

// ---------------------------------------------------------------------------
extern "C" void kernel_launch(void* const* d_in, const int* in_sizes, int n_in,
                              void* d_out, int out_size)
{
    (void)in_sizes; (void)n_in; (void)out_size;
    const float* x     = (const float*)d_in[0];
    const float* w_qkv = (const float*)d_in[1];
    const float* w_out = (const float*)d_in[2];
    const float* b_out = (const float*)d_in[3];
    const float* g     = (const float*)d_in[4];
    float* out = (float*)d_out;

    __half *p_W = nullptr, *p_Bx = nullptr, *p_Bq = nullptr, *p_A2 = nullptr;
    cudaGetSymbolAddress((void**)&p_W,   g_W2);
    cudaGetSymbolAddress((void**)&p_Bx,  g_Bx);
    cudaGetSymbolAddress((void**)&p_Bq,  g_Bq);
    cudaGetSymbolAddress((void**)&p_A2,  g_A2);

    cudaFuncSetAttribute(gemm_mma, cudaFuncAttributeMaxDynamicSharedMemorySize, SMEM1);
    cudaFuncSetAttribute(gemm_ln,  cudaFuncAttributeMaxDynamicSharedMemorySize, 2 * STG2);

    conv_w_kernel<<<QKV_ROWS, 256>>>(w_qkv);
    transpose_x<<<dim3(32, 8, BATCH), 256>>>(x);

    // QKV GEMM (single fp16, K=256) + fused q-softmax / expk / v epilogues
    gemm_mma<<<dim3(6, 32, BATCH), 256, SMEM1>>>(p_W, p_Bx);

    // context partials (fp16 inputs, register-tiled)
    context_kernel<<<dim3(BATCH * HEADS, 4), 128>>>();

    // M fold -> single fp16
    buildM_kernel<<<BATCH * HEADS, 256>>>(w_out);

    // y GEMM (K=256) + bias + LayerNorm -> d_out
    gemm_ln<<<dim3(64, 1, BATCH), 256, 2 * STG2>>>(p_A2, p_Bq, b_out, g, out);
}

// round 9
// speedup vs baseline: 5.6459x; 1.2576x over previous
#include <cuda_runtime.h>
#include <cuda_fp16.h>
#include <stdint.h>

#define BATCH   16
#define HID     256
#define HEADS   8
#define DH      32
#define NPIX    4096
#define QKV_ROWS 768
#define KP      256          // single-term fp16, K' = 256
#define NCHUNK  4            // K' / 64
#define CSEG    8            // context pixel segments

// ---------------- device scratch ------------------------------------------
__device__ __half g_ek[BATCH * 256 * NPIX];             // exp(k-4) fp16, 32 MB
__device__ __half g_v [BATCH * 256 * NPIX];             // v raw fp16, 32 MB
__device__ __half g_W2[QKV_ROWS * KP];                  // W fp16 [768,256]
__device__ __half g_Bx[BATCH * 4 * NPIX * 64];          // chunk-major x^T, 32 MB
__device__ __half g_Bq[BATCH * 4 * NPIX * 64];          // chunk-major softmaxed q^T, 32 MB
__device__ __half g_A2[BATCH * HID * KP];               // M fp16 [b,256,256]
__device__ float g_ctxp[BATCH * HEADS * CSEG * DH * DH]; // context partials
__device__ float g_kpart[BATCH * 256 * 32];             // k row sumexp partials per 128-col block

// ---------------- PTX helpers (base ISA only) ------------------------------
__device__ __forceinline__ uint32_t smem_u32(const void* p) {
    uint32_t a;
    asm("{ .reg .u64 t; cvta.to.shared.u64 t, %1; cvt.u32.u64 %0, t; }" : "=r"(a) : "l"(p));
    return a;
}
__device__ __forceinline__ void cp16(uint32_t saddr, const void* gaddr) {
    asm volatile("cp.async.cg.shared.global [%0], [%1], 16;" :: "r"(saddr), "l"(gaddr) : "memory");
}
__device__ __forceinline__ void cp_commit() {
    asm volatile("cp.async.commit_group;" ::: "memory");
}
template <int N>
__device__ __forceinline__ void cp_wait() {
    asm volatile("cp.async.wait_group %0;" :: "n"(N) : "memory");
}
__device__ __forceinline__ void ldsm_x4(uint32_t* r, uint32_t addr) {
    asm volatile("ldmatrix.sync.aligned.m8n8.x4.shared.b16 {%0,%1,%2,%3}, [%4];"
                 : "=r"(r[0]), "=r"(r[1]), "=r"(r[2]), "=r"(r[3]) : "r"(addr));
}
__device__ __forceinline__ void mma16816(float* c, const uint32_t* a, const uint32_t* b) {
    asm volatile(
        "mma.sync.aligned.m16n8k16.row.col.f32.f16.f16.f32 "
        "{%0,%1,%2,%3}, {%4,%5,%6,%7}, {%8,%9}, {%0,%1,%2,%3};"
        : "+f"(c[0]), "+f"(c[1]), "+f"(c[2]), "+f"(c[3])
        : "r"(a[0]), "r"(a[1]), "r"(a[2]), "r"(a[3]), "r"(b[0]), "r"(b[1]));
}

#define LDS_B 144
#define OP1 (128 * LDS_B)
#define STG1 (2 * OP1)           // 36864 per stage
#define SMEM1 (3 * STG1)         // 110592, 3 stages

// ---------------------------------------------------------------------------
// GEMM1 + fused epilogues. 256 threads, 8 warps of 64x32, CTA 128x128, BK=64.
// bx 0-1: q (softmax -> g_Bq fp16); 2-3: k (exp(k-4) fp16 + row sums);
// 4-5: v (raw fp16).
// ---------------------------------------------------------------------------
__global__ __launch_bounds__(256, 2) void gemm_mma(
    const __half* __restrict__ A, const __half* __restrict__ B)
{
    extern __shared__ char smem[];
    const uint32_t sb = smem_u32(smem);
    const int tid = threadIdx.x;
    const int wid = tid >> 5;
    const int lane = tid & 31;
    const int bx = blockIdx.x, by = blockIdx.y, b = blockIdx.z;

    const char* Ab = (const char*)(A + (long)bx * 128 * KP);
    const char* Bb = (const char*)B + ((long)b * 4 * NPIX + (long)by * 128) * 128;

    const int wm = (wid >> 2) * 64;
    const int wn = (wid & 3) * 32;

    float acc[4][4][4];
    #pragma unroll
    for (int i = 0; i < 4; ++i)
        #pragma unroll
        for (int j = 0; j < 4; ++j)
            #pragma unroll
            for (int k = 0; k < 4; ++k) acc[i][j][k] = 0.f;

    const int r_ld = tid >> 3;              // 0..31
    const int c16 = (tid & 7) * 16;
    auto cp_chunk = [&](int c) {
        const uint32_t as = sb + (c % 3) * STG1;
        const uint32_t bs = as + OP1;
        const long akb = (long)c * 128;
        const long bko = (long)c * NPIX * 128;
        #pragma unroll
        for (int i = 0; i < 4; ++i) {
            const int r = r_ld + i * 32;
            const uint32_t so = r * LDS_B + c16;
            cp16(as + so, Ab + (long)r * (KP * 2) + akb + c16);
            cp16(bs + so, Bb + bko + (long)r * 128 + c16);
        }
        cp_commit();
    };

    const int a_row = lane & 15;
    const int a_koff = (lane >> 4) * 16;
    const int b_row = lane & 7;
    const int b_n8 = (lane >> 4) * 8;
    const int b_koff = ((lane >> 3) & 1) * 16;

    cp_chunk(0);
    cp_chunk(1);

    for (int c = 0; c < NCHUNK; ++c) {
        if (c < NCHUNK - 1) cp_wait<1>(); else cp_wait<0>();
        __syncthreads();
        if (c + 2 < NCHUNK) cp_chunk(c + 2);

        const uint32_t as = sb + (c % 3) * STG1;
        const uint32_t bs = as + OP1;
        #pragma unroll
        for (int ks = 0; ks < 4; ++ks) {
            uint32_t afr[4][4], bfr[4][2];
            #pragma unroll
            for (int mt = 0; mt < 4; ++mt)
                ldsm_x4(afr[mt], as + (wm + mt * 16 + a_row) * LDS_B + ks * 32 + a_koff);
            #pragma unroll
            for (int np = 0; np < 2; ++np) {
                uint32_t bq[4];
                ldsm_x4(bq, bs + (wn + np * 16 + b_n8 + b_row) * LDS_B + ks * 32 + b_koff);
                bfr[np * 2][0] = bq[0]; bfr[np * 2][1] = bq[1];
                bfr[np * 2 + 1][0] = bq[2]; bfr[np * 2 + 1][1] = bq[3];
            }
            #pragma unroll
            for (int mt = 0; mt < 4; ++mt)
                #pragma unroll
                for (int nt = 0; nt < 4; ++nt)
                    mma16816(acc[mt][nt], afr[mt], bfr[nt]);
        }
    }

    const int er = lane >> 2;
    const int ec = (lane & 3) * 2;

    if (bx >= 4) {
        // ---- v: raw fp16 ----------------------------------------------------
        __half* Vb = g_v + ((long)b * 256 + (long)(bx - 4) * 128) * 4096 + by * 128;
        #pragma unroll
        for (int mt = 0; mt < 4; ++mt)
            #pragma unroll
            for (int nt = 0; nt < 4; ++nt) {
                const long r0 = wm + mt * 16 + er;
                const int c0 = wn + nt * 8 + ec;
                *reinterpret_cast<__half2*>(Vb + r0 * 4096 + c0) =
                    __floats2half2_rn(acc[mt][nt][0], acc[mt][nt][1]);
                *reinterpret_cast<__half2*>(Vb + (r0 + 8) * 4096 + c0) =
                    __floats2half2_rn(acc[mt][nt][2], acc[mt][nt][3]);
            }
        return;
    }

    if (bx >= 2) {
        // ---- k: exp(k-4) fp16 + row-sum partials ---------------------------
        __half* Ek = g_ek + ((long)b * 256 + (long)(bx - 2) * 128) * 4096 + by * 128;
        float rs[8];
        #pragma unroll
        for (int i = 0; i < 8; ++i) rs[i] = 0.f;
        #pragma unroll
        for (int mt = 0; mt < 4; ++mt)
            #pragma unroll
            for (int nt = 0; nt < 4; ++nt) {
                const float e0 = __expf(acc[mt][nt][0] - 4.f);
                const float e1 = __expf(acc[mt][nt][1] - 4.f);
                const float e2 = __expf(acc[mt][nt][2] - 4.f);
                const float e3 = __expf(acc[mt][nt][3] - 4.f);
                const long r0 = wm + mt * 16 + er;
                const int c0 = wn + nt * 8 + ec;
                *reinterpret_cast<__half2*>(Ek + r0 * 4096 + c0) = __floats2half2_rn(e0, e1);
                *reinterpret_cast<__half2*>(Ek + (r0 + 8) * 4096 + c0) = __floats2half2_rn(e2, e3);
                rs[mt * 2] += e0 + e1;
                rs[mt * 2 + 1] += e2 + e3;
            }
        #pragma unroll
        for (int off = 1; off < 4; off <<= 1)
            #pragma unroll
            for (int i = 0; i < 8; ++i)
                rs[i] += __shfl_xor_sync(0xFFFFFFFFu, rs[i], off);

        float* ssum = (float*)smem;   // [128 rows][4 col-quarters]
        __syncthreads();
        if ((lane & 3) == 0) {
            const int wq = wid & 3;
            #pragma unroll
            for (int mt = 0; mt < 4; ++mt)
                #pragma unroll
                for (int h2 = 0; h2 < 2; ++h2)
                    ssum[(wm + mt * 16 + er + h2 * 8) * 4 + wq] = rs[mt * 2 + h2];
        }
        __syncthreads();
        if (tid < 128)
            g_kpart[((long)b * 256 + (bx - 2) * 128 + tid) * 32 + by] =
                ssum[tid * 4] + ssum[tid * 4 + 1] + ssum[tid * 4 + 2] + ssum[tid * 4 + 3];
        return;
    }

    // ---- q: stage to smem, softmax over d, emit fp16 chunk-major -----------
    float* sfl = (float*)smem;
    __syncthreads();
    #pragma unroll
    for (int mt = 0; mt < 4; ++mt)
        #pragma unroll
        for (int nt = 0; nt < 4; ++nt) {
            const int r0 = wm + mt * 16 + er;
            const int c0 = wn + nt * 8 + ec;
            sfl[r0 * 129 + c0] = acc[mt][nt][0];
            sfl[r0 * 129 + c0 + 1] = acc[mt][nt][1];
            sfl[(r0 + 8) * 129 + c0] = acc[mt][nt][2];
            sfl[(r0 + 8) * 129 + c0 + 1] = acc[mt][nt][3];
        }
    __syncthreads();

    #pragma unroll
    for (int t = tid; t < 512; t += 256) {
        const int hb = t >> 7;
        const int col = t & 127;
        float v[DH];
        float m = -1e30f;
        #pragma unroll
        for (int d = 0; d < DH; ++d) {
            v[d] = sfl[(hb * 32 + d) * 129 + col];
            m = fmaxf(m, v[d]);
        }
        float s = 0.f;
        #pragma unroll
        for (int d = 0; d < DH; ++d) { v[d] = __expf(v[d] - m); s += v[d]; }
        const float inv = 0.1767766952966369f / s;
        __align__(16) __half o[DH];
        #pragma unroll
        for (int d = 0; d < DH; ++d) o[d] = __float2half(v[d] * inv);

        const int gh = bx * 4 + hb;
        const long gcol = (long)by * 128 + col;
        __half* ob = g_Bq + (((long)b * 4 + (gh >> 1)) * NPIX + gcol) * 64 + (gh & 1) * 32;
        #pragma unroll
        for (int i = 0; i < 4; ++i)
            reinterpret_cast<uint4*>(ob)[i] = reinterpret_cast<const uint4*>(o)[i];
    }
}

// ---------------------------------------------------------------------------
// GEMM2 + fused bias + LayerNorm. CTA tile 256x64. 2-stage cp.async.
// ---------------------------------------------------------------------------
#define A2_ST (256 * LDS_B)
#define B2_ST (64 * LDS_B)
#define STG2  (A2_ST + B2_ST)

__global__ __launch_bounds__(256, 2) void gemm_ln(
    const __half* __restrict__ A, const __half* __restrict__ B,
    const float* __restrict__ bout, const float* __restrict__ gam,
    float* __restrict__ out)
{
    extern __shared__ char smem[];
    const uint32_t sb = smem_u32(smem);
    const int tid = threadIdx.x;
    const int wid = tid >> 5;
    const int lane = tid & 31;
    const int b = blockIdx.z;
    const int n0 = blockIdx.x * 64;

    const char* Ab = (const char*)(A + (long)b * HID * KP);
    const char* Bb = (const char*)B + ((long)b * 4 * NPIX + n0) * 128;
    float* Cb = out + (long)b * HID * NPIX + n0;

    const int wm = (wid >> 1) * 64;
    const int wn = (wid & 1) * 32;

    float acc[4][4][4];
    #pragma unroll
    for (int i = 0; i < 4; ++i)
        #pragma unroll
        for (int j = 0; j < 4; ++j)
            #pragma unroll
            for (int k = 0; k < 4; ++k) acc[i][j][k] = 0.f;

    const int r_ld = tid >> 3;
    const int c16 = (tid & 7) * 16;
    auto cp_chunk = [&](int c, int s) {
        const uint32_t as = sb + s * STG2;
        const uint32_t bs = as + A2_ST;
        const long akb = (long)c * 128;
        const long bko = (long)c * NPIX * 128;
        #pragma unroll
        for (int i = 0; i < 8; ++i) {
            const int r = r_ld + i * 32;
            cp16(as + r * LDS_B + c16, Ab + (long)r * (KP * 2) + akb + c16);
        }
        #pragma unroll
        for (int i = 0; i < 2; ++i) {
            const int r = r_ld + i * 32;
            cp16(bs + r * LDS_B + c16, Bb + bko + (long)r * 128 + c16);
        }
        cp_commit();
    };

    const int a_row = lane & 15;
    const int a_koff = (lane >> 4) * 16;
    const int b_row = lane & 7;
    const int b_n8 = (lane >> 4) * 8;
    const int b_koff = ((lane >> 3) & 1) * 16;

    cp_chunk(0, 0);

    for (int c = 0; c < NCHUNK; ++c) {
        const int s = c & 1;
        if (c + 1 < NCHUNK) cp_chunk(c + 1, s ^ 1);
        if (c + 1 < NCHUNK) cp_wait<1>(); else cp_wait<0>();
        __syncthreads();

        const uint32_t as = sb + s * STG2;
        const uint32_t bs = as + A2_ST;
        #pragma unroll
        for (int ks = 0; ks < 4; ++ks) {
            uint32_t afr[4][4], bfr[4][2];
            #pragma unroll
            for (int mt = 0; mt < 4; ++mt)
                ldsm_x4(afr[mt], as + (wm + mt * 16 + a_row) * LDS_B + ks * 32 + a_koff);
            #pragma unroll
            for (int np = 0; np < 2; ++np) {
                uint32_t bq[4];
                ldsm_x4(bq, bs + (wn + np * 16 + b_n8 + b_row) * LDS_B + ks * 32 + b_koff);
                bfr[np * 2][0] = bq[0]; bfr[np * 2][1] = bq[1];
                bfr[np * 2 + 1][0] = bq[2]; bfr[np * 2 + 1][1] = bq[3];
            }
            #pragma unroll
            for (int mt = 0; mt < 4; ++mt)
                #pragma unroll
                for (int nt = 0; nt < 4; ++nt)
                    mma16816(acc[mt][nt], afr[mt], bfr[nt]);
        }
        __syncthreads();
    }

    const int er = lane >> 2;
    const int ec = (lane & 3) * 2;

    float bo[8], ga[8];
    #pragma unroll
    for (int mt = 0; mt < 4; ++mt) {
        const int r0 = wm + mt * 16 + er;
        bo[mt * 2] = bout[r0];        bo[mt * 2 + 1] = bout[r0 + 8];
        ga[mt * 2] = gam[r0];         ga[mt * 2 + 1] = gam[r0 + 8];
    }

    float cs[4][2], cq[4][2];
    #pragma unroll
    for (int nt = 0; nt < 4; ++nt)
        #pragma unroll
        for (int par = 0; par < 2; ++par) {
            float s = 0.f, q = 0.f;
            #pragma unroll
            for (int mt = 0; mt < 4; ++mt) {
                float v0 = acc[mt][nt][par]     + bo[mt * 2];
                float v1 = acc[mt][nt][par + 2] + bo[mt * 2 + 1];
                acc[mt][nt][par] = v0;
                acc[mt][nt][par + 2] = v1;
                s += v0 + v1;
                q += v0 * v0 + v1 * v1;
            }
            cs[nt][par] = s;
            cq[nt][par] = q;
        }
    #pragma unroll
    for (int off = 4; off < 32; off <<= 1)
        #pragma unroll
        for (int nt = 0; nt < 4; ++nt)
            #pragma unroll
            for (int par = 0; par < 2; ++par) {
                cs[nt][par] += __shfl_xor_sync(0xFFFFFFFFu, cs[nt][par], off);
                cq[nt][par] += __shfl_xor_sync(0xFFFFFFFFu, cq[nt][par], off);
            }

    float* red = (float*)smem;
    float2* lnp = (float2*)(smem + 2048);
    __syncthreads();
    if (er == 0) {
        const int wr = wid >> 1;
        #pragma unroll
        for (int nt = 0; nt < 4; ++nt)
            #pragma unroll
            for (int par = 0; par < 2; ++par) {
                const int col = wn + nt * 8 + ec + par;
                red[(wr * 64 + col) * 2]     = cs[nt][par];
                red[(wr * 64 + col) * 2 + 1] = cq[nt][par];
            }
    }
    __syncthreads();
    if (tid < 64) {
        float s = 0.f, q = 0.f;
        #pragma unroll
        for (int wr = 0; wr < 4; ++wr) {
            s += red[(wr * 64 + tid) * 2];
            q += red[(wr * 64 + tid) * 2 + 1];
        }
        const float mean = s * (1.f / 256.f);
        const float var = q * (1.f / 256.f) - mean * mean;
        lnp[tid] = make_float2(mean, rsqrtf(var + 1e-5f));
    }
    __syncthreads();

    #pragma unroll
    for (int mt = 0; mt < 4; ++mt)
        #pragma unroll
        for (int nt = 0; nt < 4; ++nt) {
            const float2 l0 = lnp[wn + nt * 8 + ec];
            const float2 l1 = lnp[wn + nt * 8 + ec + 1];
            float* p0 = Cb + (long)(wm + mt * 16 + er) * 4096 + wn + nt * 8 + ec;
            *reinterpret_cast<float2*>(p0) = make_float2(
                (acc[mt][nt][0] - l0.x) * l0.y * ga[mt * 2],
                (acc[mt][nt][1] - l1.x) * l1.y * ga[mt * 2]);
            *reinterpret_cast<float2*>(p0 + 8L * 4096) = make_float2(
                (acc[mt][nt][2] - l0.x) * l0.y * ga[mt * 2 + 1],
                (acc[mt][nt][3] - l1.x) * l1.y * ga[mt * 2 + 1]);
        }
}

// ---------------------------------------------------------------------------
__global__ __launch_bounds__(256) void conv_w_kernel(const float* __restrict__ w)
{
    const int m = blockIdx.x, c = threadIdx.x;
    g_W2[(long)m * KP + c] = __float2half(w[m * 256 + c]);
}

// ---------------------------------------------------------------------------
__global__ __launch_bounds__(256) void transpose_x(const float* __restrict__ x)
{
    __shared__ float sm[32][129];
    const int b = blockIdx.z, c0 = blockIdx.y * 32, p0 = blockIdx.x * 128;
    const float* xb = x + ((long)b * 256 + c0) * 4096 + p0;
    const int tid = threadIdx.x;

    #pragma unroll
    for (int i = 0; i < 16; ++i) {
        const int u = tid + i * 256;
        sm[u >> 7][u & 127] = xb[(long)(u >> 7) * 4096 + (u & 127)];
    }
    __syncthreads();

    const int rr = tid >> 1, j0 = (tid & 1) * 16;
    __align__(16) __half hv[16];
    #pragma unroll
    for (int j = 0; j < 16; ++j) hv[j] = __float2half(sm[j0 + j][rr]);

    __half* ob = g_Bx + (((long)b * 4 + (c0 >> 6)) * NPIX + p0 + rr) * 64 + (c0 & 63) + j0;
    reinterpret_cast<uint4*>(ob)[0] = reinterpret_cast<const uint4*>(hv)[0];
    reinterpret_cast<uint4*>(ob)[1] = reinterpret_cast<const uint4*>(hv)[1];
}

// ---------------------------------------------------------------------------
// context via tensor cores: ctx[32,32] = ek[32,K] * v[32,K]^T per (b,h).
// grid (128 bh, 8 segs), 128 threads / 4 warps; each warp a 16-px K-slice
// of a 64-px tile, 3-stage cp.async; cross-warp reduce + ki scaling.
// ---------------------------------------------------------------------------
__global__ __launch_bounds__(128) void context_mma()
{
    __shared__ __half sK[3][DH][72];
    __shared__ __half sV[3][DH][72];
    __shared__ float red[4][DH][DH + 1];
    __shared__ float ki[DH];

    const int bh = blockIdx.x, seg = blockIdx.y;
    const int b = bh >> 3, h = bh & 7;
    const __half* kb = g_ek + ((long)b * 256 + h * DH) * 4096 + seg * 512;
    const __half* vb = g_v  + ((long)b * 256 + h * DH) * 4096 + seg * 512;

    const int tid = threadIdx.x;
    const int wid = tid >> 5;
    const int lane = tid & 31;

    if (tid < DH) {
        const float* pp = g_kpart + ((long)b * 256 + h * DH + tid) * 32;
        float s = 0.f;
        #pragma unroll
        for (int i = 0; i < 32; ++i) s += pp[i];
        ki[tid] = 1.f / s;
    }

    auto cp_stage = [&](int it) {
        const int s = it % 3;
        const int p0 = it * 64;
        #pragma unroll
        for (int i = 0; i < 2; ++i) {
            const int u = tid + i * 128;            // 0..255
            const int row = u >> 3, ce = (u & 7) * 8;
            cp16(smem_u32(&sK[s][row][ce]), kb + (long)row * 4096 + p0 + ce);
            cp16(smem_u32(&sV[s][row][ce]), vb + (long)row * 4096 + p0 + ce);
        }
        cp_commit();
    };

    float acc[2][4][4];
    #pragma unroll
    for (int i = 0; i < 2; ++i)
        #pragma unroll
        for (int j = 0; j < 4; ++j)
            #pragma unroll
            for (int k = 0; k < 4; ++k) acc[i][j][k] = 0.f;

    const int a_row = lane & 15;
    const int a_koff = (lane >> 4) * 16;
    const int b_row = lane & 7;
    const int b_n8 = (lane >> 4) * 8;
    const int b_koff = ((lane >> 3) & 1) * 16;
    const int kwb = wid * 32;                       // warp k-slice byte offset

    cp_stage(0);
    cp_stage(1);

    for (int it = 0; it < 8; ++it) {
        const int s = it % 3;
        if (it < 7) cp_wait<1>(); else cp_wait<0>();
        __syncthreads();
        if (it + 2 < 8) cp_stage(it + 2);

        const uint32_t aK = smem_u32(&sK[s][0][0]);
        const uint32_t aV = smem_u32(&sV[s][0][0]);
        uint32_t afr[2][4], bfr[4][2];
        #pragma unroll
        for (int mt = 0; mt < 2; ++mt)
            ldsm_x4(afr[mt], aK + (mt * 16 + a_row) * 144 + kwb + a_koff);
        #pragma unroll
        for (int np = 0; np < 2; ++np) {
            uint32_t bq[4];
            ldsm_x4(bq, aV + (np * 16 + b_n8 + b_row) * 144 + kwb + b_koff);
            bfr[np * 2][0] = bq[0]; bfr[np * 2][1] = bq[1];
            bfr[np * 2 + 1][0] = bq[2]; bfr[np * 2 + 1][1] = bq[3];
        }
        #pragma unroll
        for (int mt = 0; mt < 2; ++mt)
            #pragma unroll
            for (int nt = 0; nt < 4; ++nt)
                mma16816(acc[mt][nt], afr[mt], bfr[nt]);
    }

    // ---- cross-warp reduce + ki scaling -------------------------------------
    const int er = lane >> 2;
    const int ec = (lane & 3) * 2;
    #pragma unroll
    for (int mt = 0; mt < 2; ++mt)
        #pragma unroll
        for (int nt = 0; nt < 4; ++nt) {
            const int d0 = mt * 16 + er;
            const int e0 = nt * 8 + ec;
            red[wid][d0][e0]     = acc[mt][nt][0];
            red[wid][d0][e0 + 1] = acc[mt][nt][1];
            red[wid][d0 + 8][e0]     = acc[mt][nt][2];
            red[wid][d0 + 8][e0 + 1] = acc[mt][nt][3];
        }
    __syncthreads();

    float* op = g_ctxp + ((long)bh * CSEG + seg) * (DH * DH);
    const float invn = 1.f / (float)NPIX;
    #pragma unroll
    for (int i = tid; i < DH * DH; i += 128) {
        const int d = i >> 5, e = i & 31;
        const float s = red[0][d][e] + red[1][d][e] + red[2][d][e] + red[3][d][e];
        op[i] = s * ki[d] * invn;
    }
}

// ---------------------------------------------------------------------------
// buildM -> single fp16 M in g_A2
// ---------------------------------------------------------------------------
__global__ __launch_bounds__(256) void buildM_kernel(const float* __restrict__ wout)
{
    const int bh = blockIdx.x;
    const int b = bh >> 3, h = bh & 7;

    __shared__ float cs[DH][DH + 1];
    const int tid = threadIdx.x;

    for (int i = tid; i < DH * DH; i += 256) {
        float s = 0.f;
        #pragma unroll
        for (int ch = 0; ch < CSEG; ++ch)
            s += g_ctxp[((long)bh * CSEG + ch) * (DH * DH) + i];
        cs[i >> 5][i & 31] = s;
    }
    __syncthreads();

    float w[DH];
    const float* wr = wout + (long)tid * 256 + h * DH;
    #pragma unroll
    for (int e = 0; e < DH; ++e) w[e] = wr[e];

    __align__(16) __half hi[DH];
    for (int d = 0; d < DH; ++d) {
        float s = 0.f;
        #pragma unroll
        for (int e = 0; e < DH; ++e) s += w[e] * cs[d][e];
        hi[d] = __float2half(s);
    }
    __half* ob = g_A2 + ((long)b * HID + tid) * KP + h * DH;
    #pragma unroll
    for (int i = 0; i < 4; ++i)
        reinterpret_cast<uint4*>(ob)[i] = reinterpret_cast<const uint4*>(hi)[i];
}

// ---------------------------------------------------------------------------
extern "C" void kernel_launch(void* const* d_in, const int* in_sizes, int n_in,
                              void* d_out, int out_size)
{
    (void)in_sizes; (void)n_in; (void)out_size;
    const float* x     = (const float*)d_in[0];
    const float* w_qkv = (const float*)d_in[1];
    const float* w_out = (const float*)d_in[2];
    const float* b_out = (const float*)d_in[3];
    const float* g     = (const float*)d_in[4];
    float* out = (float*)d_out;

    __half *p_W = nullptr, *p_Bx = nullptr, *p_Bq = nullptr, *p_A2 = nullptr;
    cudaGetSymbolAddress((void**)&p_W,   g_W2);
    cudaGetSymbolAddress((void**)&p_Bx,  g_Bx);
    cudaGetSymbolAddress((void**)&p_Bq,  g_Bq);
    cudaGetSymbolAddress((void**)&p_A2,  g_A2);

    cudaFuncSetAttribute(gemm_mma, cudaFuncAttributeMaxDynamicSharedMemorySize, SMEM1);
    cudaFuncSetAttribute(gemm_ln,  cudaFuncAttributeMaxDynamicSharedMemorySize, 2 * STG2);

    conv_w_kernel<<<QKV_ROWS, 256>>>(w_qkv);
    transpose_x<<<dim3(32, 8, BATCH), 256>>>(x);

    // QKV GEMM (single fp16, K=256) + fused q-softmax / expk / v epilogues
    gemm_mma<<<dim3(6, 32, BATCH), 256, SMEM1>>>(p_W, p_Bx);

    // context partials via tensor cores
    context_mma<<<dim3(BATCH * HEADS, CSEG), 128>>>();

    // M fold -> single fp16
    buildM_kernel<<<BATCH * HEADS, 256>>>(w_out);

    // y GEMM (K=256) + bias + LayerNorm -> d_out
    gemm_ln<<<dim3(64, 1, BATCH), 256, 2 * STG2>>>(p_A2, p_Bq, b_out, g, out);
}